// round 3
// baseline (speedup 1.0000x reference)
#include <cuda_runtime.h>
#include <math.h>

// Problem constants
#define B_    16
#define C_    256
#define N_    1024
#define HEADS 4
#define DH    64
#define AP    68   // smem pitch (floats): 16B-aligned, conflict-avoiding

// Scratch (static device globals — no allocation in kernel_launch)
__device__ float g_xn[B_ * C_ * N_];
__device__ float g_q [B_ * HEADS * N_ * DH];
__device__ float g_k [B_ * HEADS * N_ * DH];
__device__ float g_v [B_ * HEADS * N_ * DH];
__device__ float g_ao[B_ * N_ * C_];   // attention out, [b][n][c]

// ---------------------------------------------------------------------------
// 1) GroupNorm: one block per (b, g). Group's 32 channels x 1024 spatial are
//    contiguous in memory (32768 floats).
// ---------------------------------------------------------------------------
__global__ void gn_kernel(const float* __restrict__ x,
                          const float* __restrict__ w,
                          const float* __restrict__ bias) {
    const int blk = blockIdx.x;                 // b*8 + g
    const size_t base = (size_t)blk * 32768;
    const int tid = threadIdx.x;

    double s = 0.0, s2 = 0.0;
    for (int i = tid; i < 8192; i += 256) {
        float4 v = *(const float4*)&x[base + i * 4];
        s  += (double)v.x + v.y + v.z + v.w;
        s2 += (double)v.x * v.x + (double)v.y * v.y
            + (double)v.z * v.z + (double)v.w * v.w;
    }
    __shared__ double rs[256], rs2[256];
    rs[tid] = s; rs2[tid] = s2;
    __syncthreads();
    for (int off = 128; off > 0; off >>= 1) {
        if (tid < off) { rs[tid] += rs[tid + off]; rs2[tid] += rs2[tid + off]; }
        __syncthreads();
    }
    __shared__ float smean, sinv;
    if (tid == 0) {
        double mu  = rs[0] * (1.0 / 32768.0);
        double var = rs2[0] * (1.0 / 32768.0) - mu * mu;
        smean = (float)mu;
        sinv  = (float)rsqrt(var + 1e-5);
    }
    __syncthreads();
    const float mean = smean, inv = sinv;
    const int cbase = (blk & 7) * 32;
    for (int i = tid; i < 8192; i += 256) {
        int c = cbase + (i >> 8);               // (i*4)>>10
        float sc = inv * w[c];
        float sb = bias[c] - mean * sc;
        float4 v = *(const float4*)&x[base + i * 4];
        float4 r;
        r.x = v.x * sc + sb; r.y = v.y * sc + sb;
        r.z = v.z * sc + sb; r.w = v.w * sc + sb;
        *(float4*)&g_xn[base + i * 4] = r;
    }
}

// ---------------------------------------------------------------------------
// 2) QKV GEMM per batch: C[o,n] = sum_c W[o,c] * xn[b,c,n], o in [0,768).
//    64x64 output tile, BK=16, 4x4 register micro-tile, float4 smem fragments.
//    Epilogue scatters into Q/K/V as [b][h][n][d].
// ---------------------------------------------------------------------------
__global__ void qkv_kernel(const float* __restrict__ w,
                           const float* __restrict__ bias) {
    __shared__ float At[16][AP];   // [k][o]  (transposed)
    __shared__ float Bs[16][AP];   // [k][n]
    const int tid = threadIdx.x;
    const int tx = tid & 15, ty = tid >> 4;
    const int n0 = blockIdx.x * 64;
    const int o0 = blockIdx.y * 64;
    const int b  = blockIdx.z;
    const float* xb = g_xn + (size_t)b * C_ * N_;

    float acc[4][4] = {};
    for (int kb = 0; kb < 16; kb++) {
        #pragma unroll
        for (int e = 0; e < 4; e++) {
            int lin = e * 256 + tid;
            At[lin & 15][lin >> 4] =
                w[(size_t)(o0 + (lin >> 4)) * C_ + kb * 16 + (lin & 15)];
            Bs[lin >> 6][lin & 63] =
                xb[(size_t)(kb * 16 + (lin >> 6)) * N_ + n0 + (lin & 63)];
        }
        __syncthreads();
        #pragma unroll
        for (int kk = 0; kk < 16; kk++) {
            float4 af = *(const float4*)&Bs[kk][ty * 4];   // n fragment (i)
            float4 bf = *(const float4*)&At[kk][tx * 4];   // o fragment (j)
            float av[4] = {af.x, af.y, af.z, af.w};
            float bv[4] = {bf.x, bf.y, bf.z, bf.w};
            #pragma unroll
            for (int i = 0; i < 4; i++)
                #pragma unroll
                for (int j = 0; j < 4; j++)
                    acc[i][j] += av[i] * bv[j];
        }
        __syncthreads();
    }
    const int t = o0 >> 8;            // 0:q 1:k 2:v (tile spans one t,h)
    const int h = (o0 >> 6) & 3;
    const int d0 = tx * 4;
    float* dst = (t == 0) ? g_q : ((t == 1) ? g_k : g_v);
    float4 bv4 = *(const float4*)&bias[o0 + d0];
    #pragma unroll
    for (int i = 0; i < 4; i++) {
        int n = n0 + ty * 4 + i;
        float4 r;
        r.x = acc[i][0] + bv4.x; r.y = acc[i][1] + bv4.y;
        r.z = acc[i][2] + bv4.z; r.w = acc[i][3] + bv4.w;
        *(float4*)&dst[(((size_t)b * HEADS + h) * N_ + n) * DH + d0] = r;
    }
}

// ---------------------------------------------------------------------------
// 3) Flash attention: one CTA per (b*h, 64-row Q tile). 16 K/V tiles of 64.
//    Online softmax; Q,K,P stored k-major in smem for float4 fragments.
//    Output written to g_ao as [b][n][c], c = h*64+d.
// ---------------------------------------------------------------------------
__global__ void attn_kernel() {
    extern __shared__ float sm[];
    float* Qt = sm;                 // [d][r]
    float* Kt = Qt + 64 * AP;       // [d][m]
    float* Vs = Kt + 64 * AP;       // [m][d]
    float* Pt = Vs + 64 * AP;       // [m][r]
    const int tid = threadIdx.x;
    const int tx = tid & 15, ty = tid >> 4;
    const int bh = blockIdx.y;
    const int b = bh >> 2, h = bh & 3;
    const int n0 = blockIdx.x * 64;
    const float* qb = g_q + ((size_t)bh * N_ + n0) * DH;
    const float* kb = g_k + (size_t)bh * N_ * DH;
    const float* vb = g_v + (size_t)bh * N_ * DH;

    // Load full 64x64 Q tile (4096 floats): float4 per thread x 4 passes.
    #pragma unroll
    for (int e = 0; e < 4; e++) {
        int lin4 = (e * 256 + tid) * 4;
        int row = lin4 >> 6, d = lin4 & 63;
        float4 qv = *(const float4*)&qb[lin4];
        Qt[(d + 0) * AP + row] = qv.x;
        Qt[(d + 1) * AP + row] = qv.y;
        Qt[(d + 2) * AP + row] = qv.z;
        Qt[(d + 3) * AP + row] = qv.w;
    }

    float m_[4], l_[4], acc[4][4];
    #pragma unroll
    for (int i = 0; i < 4; i++) {
        m_[i] = -1e30f; l_[i] = 0.f;
        #pragma unroll
        for (int j = 0; j < 4; j++) acc[i][j] = 0.f;
    }

    for (int t = 0; t < 16; t++) {
        __syncthreads();   // prev O-update done (and Q load on first iter)
        const float* kt = kb + t * 64 * DH;
        const float* vt = vb + t * 64 * DH;
        #pragma unroll
        for (int e = 0; e < 4; e++) {
            int lin4 = (e * 256 + tid) * 4;
            int row = lin4 >> 6, d = lin4 & 63;
            float4 kv = *(const float4*)&kt[lin4];
            Kt[(d + 0) * AP + row] = kv.x;
            Kt[(d + 1) * AP + row] = kv.y;
            Kt[(d + 2) * AP + row] = kv.z;
            Kt[(d + 3) * AP + row] = kv.w;
            float4 vv = *(const float4*)&vt[lin4];
            *(float4*)&Vs[row * AP + d] = vv;
        }
        __syncthreads();

        float s[4][4] = {};
        #pragma unroll 8
        for (int kk = 0; kk < 64; kk++) {
            float4 af = *(const float4*)&Qt[kk * AP + ty * 4];
            float4 bf = *(const float4*)&Kt[kk * AP + tx * 4];
            float av[4] = {af.x, af.y, af.z, af.w};
            float bv[4] = {bf.x, bf.y, bf.z, bf.w};
            #pragma unroll
            for (int i = 0; i < 4; i++)
                #pragma unroll
                for (int j = 0; j < 4; j++)
                    s[i][j] += av[i] * bv[j];
        }

        #pragma unroll
        for (int i = 0; i < 4; i++) {
            #pragma unroll
            for (int j = 0; j < 4; j++) s[i][j] *= 0.125f;   // 1/sqrt(64)
            float mx = fmaxf(fmaxf(s[i][0], s[i][1]), fmaxf(s[i][2], s[i][3]));
            #pragma unroll
            for (int off = 8; off > 0; off >>= 1)
                mx = fmaxf(mx, __shfl_xor_sync(0xffffffffu, mx, off));
            float nm = fmaxf(m_[i], mx);
            float al = __expf(m_[i] - nm);
            float ps = 0.f;
            #pragma unroll
            for (int j = 0; j < 4; j++) {
                float p = __expf(s[i][j] - nm);
                ps += p;
                Pt[(tx * 4 + j) * AP + ty * 4 + i] = p;
            }
            #pragma unroll
            for (int off = 8; off > 0; off >>= 1)
                ps += __shfl_xor_sync(0xffffffffu, ps, off);
            l_[i] = l_[i] * al + ps;
            m_[i] = nm;
            #pragma unroll
            for (int j = 0; j < 4; j++) acc[i][j] *= al;
        }
        __syncthreads();

        #pragma unroll 8
        for (int mm = 0; mm < 64; mm++) {
            float4 pf = *(const float4*)&Pt[mm * AP + ty * 4];
            float4 vf = *(const float4*)&Vs[mm * AP + tx * 4];
            float pv[4] = {pf.x, pf.y, pf.z, pf.w};
            float vv[4] = {vf.x, vf.y, vf.z, vf.w};
            #pragma unroll
            for (int i = 0; i < 4; i++)
                #pragma unroll
                for (int j = 0; j < 4; j++)
                    acc[i][j] += pv[i] * vv[j];
        }
    }

    float* aob = g_ao + ((size_t)b * N_ + n0) * C_ + h * DH;
    #pragma unroll
    for (int i = 0; i < 4; i++) {
        float inv = 1.0f / l_[i];
        float4 r;
        r.x = acc[i][0] * inv; r.y = acc[i][1] * inv;
        r.z = acc[i][2] * inv; r.w = acc[i][3] * inv;
        *(float4*)&aob[(size_t)(ty * 4 + i) * C_ + tx * 4] = r;
    }
}

// ---------------------------------------------------------------------------
// 4) Proj GEMM + bias + residual: out[b,o,n] = sum_c W[o,c]*AO[b,n,c] + pb + x
// ---------------------------------------------------------------------------
__global__ void proj_kernel(const float* __restrict__ w,
                            const float* __restrict__ bias,
                            const float* __restrict__ x,
                            float* __restrict__ out) {
    __shared__ float At[16][AP];   // [k][o]
    __shared__ float Bs[16][AP];   // [k][n]
    const int tid = threadIdx.x;
    const int tx = tid & 15, ty = tid >> 4;
    const int n0 = blockIdx.x * 64;
    const int o0 = blockIdx.y * 64;
    const int b  = blockIdx.z;

    float acc[4][4] = {};
    for (int kb = 0; kb < 16; kb++) {
        #pragma unroll
        for (int e = 0; e < 4; e++) {
            int lin = e * 256 + tid;
            At[lin & 15][lin >> 4] =
                w[(size_t)(o0 + (lin >> 4)) * C_ + kb * 16 + (lin & 15)];
            Bs[lin & 15][lin >> 4] =
                g_ao[((size_t)b * N_ + n0 + (lin >> 4)) * C_ + kb * 16 + (lin & 15)];
        }
        __syncthreads();
        #pragma unroll
        for (int kk = 0; kk < 16; kk++) {
            float4 af = *(const float4*)&At[kk][ty * 4];   // o fragment (i)
            float4 bf = *(const float4*)&Bs[kk][tx * 4];   // n fragment (j)
            float av[4] = {af.x, af.y, af.z, af.w};
            float bv[4] = {bf.x, bf.y, bf.z, bf.w};
            #pragma unroll
            for (int i = 0; i < 4; i++)
                #pragma unroll
                for (int j = 0; j < 4; j++)
                    acc[i][j] += av[i] * bv[j];
        }
        __syncthreads();
    }
    #pragma unroll
    for (int i = 0; i < 4; i++) {
        int o = o0 + ty * 4 + i;
        float pb = bias[o];
        size_t base = ((size_t)b * C_ + o) * N_ + n0 + tx * 4;
        float4 sk = *(const float4*)&x[base];
        float4 r;
        r.x = acc[i][0] + pb + sk.x; r.y = acc[i][1] + pb + sk.y;
        r.z = acc[i][2] + pb + sk.z; r.w = acc[i][3] + pb + sk.w;
        *(float4*)&out[base] = r;
    }
}

// ---------------------------------------------------------------------------
extern "C" void kernel_launch(void* const* d_in, const int* in_sizes, int n_in,
                              void* d_out, int out_size) {
    const float* x     = (const float*)d_in[0];
    const float* gn_w  = (const float*)d_in[1];
    const float* gn_b  = (const float*)d_in[2];
    const float* qkv_w = (const float*)d_in[3];
    const float* qkv_b = (const float*)d_in[4];
    const float* prj_w = (const float*)d_in[5];
    const float* prj_b = (const float*)d_in[6];
    float* out = (float*)d_out;

    const int attn_smem = 4 * 64 * AP * (int)sizeof(float);  // 69632 B
    cudaFuncSetAttribute(attn_kernel,
                         cudaFuncAttributeMaxDynamicSharedMemorySize, attn_smem);

    gn_kernel<<<B_ * 8, 256>>>(x, gn_w, gn_b);
    qkv_kernel<<<dim3(N_ / 64, 768 / 64, B_), 256>>>(qkv_w, qkv_b);
    attn_kernel<<<dim3(N_ / 64, B_ * HEADS), 256, attn_smem>>>();
    proj_kernel<<<dim3(N_ / 64, C_ / 64, B_), 256>>>(prj_w, prj_b, x, out);
}

// round 6
// speedup vs baseline: 3.0539x; 3.0539x over previous
#include <cuda_runtime.h>
#include <math.h>
#include <stdint.h>

#define B_    16
#define C_    256
#define N_    1024
#define HEADS 4
#define DH    64
#define BH    (B_*HEADS)
#define PTF   36        // smem pitch in floats for 32-wide k tiles

// ---------------- scratch (fp32 everywhere; only tf32 rounding in GEMMs) ---
__device__ __align__(256) float g_xnt[B_*N_*C_];          // [b][n][c]
__device__ __align__(256) float g_q  [BH*N_*DH];          // [bh][n][d]
__device__ __align__(256) float g_k  [BH*N_*DH];          // [bh][n][d]
__device__ __align__(256) float g_vt [BH*DH*N_];          // [bh][d][m]
__device__ __align__(256) float g_s  [(size_t)BH*N_*N_];  // [bh][q][k]
__device__ __align__(256) float g_ao [B_*N_*C_];          // [b][n][c]

// ---------------- tf32 mma helpers -----------------------------------------
__device__ __forceinline__ float tf32r(float x) {
    uint32_t o;
    asm("cvt.rna.tf32.f32 %0, %1;" : "=r"(o) : "f"(x));
    return __uint_as_float(o);
}
__device__ __forceinline__ void mma_tf32(float c[4], const float a[4],
                                         float b0, float b1) {
    asm volatile(
        "mma.sync.aligned.m16n8k8.row.col.f32.tf32.tf32.f32 "
        "{%0,%1,%2,%3}, {%4,%5,%6,%7}, {%8,%9}, {%0,%1,%2,%3};"
        : "+f"(c[0]), "+f"(c[1]), "+f"(c[2]), "+f"(c[3])
        : "r"(__float_as_uint(a[0])), "r"(__float_as_uint(a[1])),
          "r"(__float_as_uint(a[2])), "r"(__float_as_uint(a[3])),
          "r"(__float_as_uint(b0)),  "r"(__float_as_uint(b1)));
}
// store logical k8 group [j0..j3 | j4..j7] interleaved: phys = (j<4)?2j:2(j-4)+1
__device__ __forceinline__ void sts_perm(float* srow, int g4,
                                         float4 v0, float4 v1) {
    srow[g4 + 0] = tf32r(v0.x); srow[g4 + 2] = tf32r(v0.y);
    srow[g4 + 4] = tf32r(v0.z); srow[g4 + 6] = tf32r(v0.w);
    srow[g4 + 1] = tf32r(v1.x); srow[g4 + 3] = tf32r(v1.y);
    srow[g4 + 5] = tf32r(v1.z); srow[g4 + 7] = tf32r(v1.w);
}

// CTA 128 x (NJ*16) GEMM: C = A(128 x K, lda) . B(NJ*16 x K, ldb)^T, K-major.
// 256 thr / 8 warps (4m x 2n), BK=32, double-buffered, k8-interleaved smem.
template<int NJ, int KT>
__device__ __forceinline__ void gemm_tf32(const float* gA, int lda,
                                          const float* gB, int ldb,
                                          float* sA, float* sB,
                                          float (&c)[2][NJ][4]) {
    const int tid = threadIdx.x, lane = tid & 31;
    const int wm = (tid >> 5) & 3, wn = tid >> 7;
    const int r0 = tid >> 2, g4 = (tid & 3) * 8;
    constexpr int BR   = NJ * 16;       // B tile rows
    constexpr int ABUF = 128 * PTF;
    constexpr int BBUF = BR * PTF;

    float4 pa[2][2], pb[BR / 64][2];
    auto ldg = [&](int kt) {
        #pragma unroll
        for (int h = 0; h < 2; h++) {
            pa[0][h] = *(const float4*)(gA + (size_t)r0 * lda + kt * 32 + g4 + h * 4);
            pa[1][h] = *(const float4*)(gA + (size_t)(r0 + 64) * lda + kt * 32 + g4 + h * 4);
            #pragma unroll
            for (int rb = 0; rb < BR / 64; rb++)
                pb[rb][h] = *(const float4*)(gB + (size_t)(r0 + rb * 64) * ldb
                                             + kt * 32 + g4 + h * 4);
        }
    };
    auto sts = [&](int buf) {
        float* dA = sA + buf * ABUF;
        float* dB = sB + buf * BBUF;
        sts_perm(dA + r0 * PTF, g4, pa[0][0], pa[0][1]);
        sts_perm(dA + (r0 + 64) * PTF, g4, pa[1][0], pa[1][1]);
        #pragma unroll
        for (int rb = 0; rb < BR / 64; rb++)
            sts_perm(dB + (r0 + rb * 64) * PTF, g4, pb[rb][0], pb[rb][1]);
    };

    ldg(0); sts(0);
    __syncthreads();
    for (int kt = 0; kt < KT; kt++) {
        const float* cA = sA + (kt & 1) * ABUF;
        const float* cB = sB + (kt & 1) * BBUF;
        if (kt + 1 < KT) ldg(kt + 1);
        #pragma unroll
        for (int g = 0; g < 4; g++) {
            float a[2][4];
            #pragma unroll
            for (int i = 0; i < 2; i++) {
                float2 lo = *(const float2*)&cA[(wm * 32 + i * 16 + (lane >> 2)) * PTF
                                                + g * 8 + 2 * (lane & 3)];
                float2 hi = *(const float2*)&cA[(wm * 32 + i * 16 + 8 + (lane >> 2)) * PTF
                                                + g * 8 + 2 * (lane & 3)];
                a[i][0] = lo.x; a[i][1] = hi.x; a[i][2] = lo.y; a[i][3] = hi.y;
            }
            #pragma unroll
            for (int j = 0; j < NJ; j++) {
                float2 bv = *(const float2*)&cB[(wn * (NJ * 8) + j * 8 + (lane >> 2)) * PTF
                                                + g * 8 + 2 * (lane & 3)];
                #pragma unroll
                for (int i = 0; i < 2; i++)
                    mma_tf32(c[i][j], a[i], bv.x, bv.y);
            }
        }
        if (kt + 1 < KT) sts((kt + 1) & 1);
        __syncthreads();
    }
}

// ---------------- 1) GroupNorm -> fp32 xnt[b][n][c] (tiled transpose) ------
__global__ void gn_kernel(const float* __restrict__ x,
                          const float* __restrict__ w,
                          const float* __restrict__ bias) {
    const int blk = blockIdx.x;                 // b*8 + g
    const size_t base = (size_t)blk * 32768;
    const int tid = threadIdx.x;

    double s = 0.0, s2 = 0.0;
    for (int i = tid; i < 8192; i += 256) {
        float4 v = *(const float4*)&x[base + i * 4];
        s  += (double)v.x + v.y + v.z + v.w;
        s2 += (double)v.x * v.x + (double)v.y * v.y
            + (double)v.z * v.z + (double)v.w * v.w;
    }
    __shared__ double rs[256], rs2[256];
    rs[tid] = s; rs2[tid] = s2;
    __syncthreads();
    for (int off = 128; off > 0; off >>= 1) {
        if (tid < off) { rs[tid] += rs[tid + off]; rs2[tid] += rs2[tid + off]; }
        __syncthreads();
    }
    __shared__ float smean, sinv;
    if (tid == 0) {
        double mu  = rs[0] * (1.0 / 32768.0);
        double var = rs2[0] * (1.0 / 32768.0) - mu * mu;
        smean = (float)mu;
        sinv  = (float)rsqrt(var + 1e-5);
    }
    __syncthreads();
    const int cbase = (blk & 7) * 32;
    __shared__ float ssc[32], ssb[32];
    if (tid < 32) {
        int cc = cbase + tid;
        float sc = sinv * w[cc];
        ssc[tid] = sc;
        ssb[tid] = bias[cc] - smean * sc;
    }
    __syncthreads();

    __shared__ float tile[128][33];             // [n][c]
    const int b = blk >> 3;
    for (int nt = 0; nt < 8; nt++) {
        #pragma unroll
        for (int k2 = 0; k2 < 16; k2++) {
            int idx = tid + k2 * 256;
            int cc = idx >> 7, nn = idx & 127;
            tile[nn][cc] = x[base + (size_t)cc * 1024 + nt * 128 + nn]
                           * ssc[cc] + ssb[cc];
        }
        __syncthreads();
        #pragma unroll
        for (int k2 = 0; k2 < 4; k2++) {
            int idx = tid + k2 * 256;
            int nn = idx >> 3, c4 = (idx & 7) * 4;
            float4 o;
            o.x = tile[nn][c4];     o.y = tile[nn][c4 + 1];
            o.z = tile[nn][c4 + 2]; o.w = tile[nn][c4 + 3];
            *(float4*)&g_xnt[((size_t)(b * N_ + nt * 128 + nn)) * C_ + cbase + c4] = o;
        }
        __syncthreads();
    }
}

// ---------------- 2) QKV: D[n][o] = xnt . Wqkv^T ---------------------------
__global__ __launch_bounds__(256) void qkv_tc(const float* __restrict__ wq,
                                              const float* __restrict__ bias) {
    extern __shared__ float sm[];
    float* sA = sm;
    float* sB = sm + 2 * 128 * PTF;
    const int n0 = blockIdx.x * 128, o0 = blockIdx.y * 128, b = blockIdx.z;
    float c[2][8][4] = {};
    gemm_tf32<8, 8>(g_xnt + ((size_t)(b * N_ + n0)) * C_, C_,
                    wq + (size_t)o0 * C_, C_, sA, sB, c);

    const int lane = threadIdx.x & 31;
    const int wm = (threadIdx.x >> 5) & 3, wn = threadIdx.x >> 7;
    const int t = o0 >> 8;                      // 0:q 1:k 2:v
    const int b4 = b * HEADS;
    #pragma unroll
    for (int i = 0; i < 2; i++) {
        int m = n0 + wm * 32 + i * 16 + (lane >> 2);
        #pragma unroll
        for (int j = 0; j < 8; j++) {
            int o = o0 + wn * 64 + j * 8 + (lane & 3) * 2;
            float b0v = bias[o], b1v = bias[o + 1];
            if (t < 2) {
                float* dst = (t == 0) ? g_q : g_k;
                int h = (o >> 6) & 3, d = o & 63;
                size_t rb = ((size_t)(b4 + h) * N_) * DH + d;
                float2 w0, w1;
                w0.x = c[i][j][0] + b0v; w0.y = c[i][j][1] + b1v;
                w1.x = c[i][j][2] + b0v; w1.y = c[i][j][3] + b1v;
                *(float2*)&dst[rb + (size_t)m * DH] = w0;
                *(float2*)&dst[rb + (size_t)(m + 8) * DH] = w1;
            } else {
                int og = o - 512;
                size_t rb = ((size_t)(b4 + (og >> 6)) * DH + (og & 63)) * N_;
                g_vt[rb + m]            = c[i][j][0] + b0v;
                g_vt[rb + N_ + m]       = c[i][j][1] + b1v;
                g_vt[rb + m + 8]        = c[i][j][2] + b0v;
                g_vt[rb + N_ + m + 8]   = c[i][j][3] + b1v;
            }
        }
    }
}

// ---------------- 3) S = scale * Q K^T -------------------------------------
__global__ __launch_bounds__(256) void s_tc() {
    extern __shared__ float sm[];
    float* sA = sm;
    float* sB = sm + 2 * 128 * PTF;
    const int k0 = blockIdx.x * 128, q0 = blockIdx.y * 128, bh = blockIdx.z;
    float c[2][8][4] = {};
    gemm_tf32<8, 2>(g_q + ((size_t)bh * N_ + q0) * DH, DH,
                    g_k + ((size_t)bh * N_ + k0) * DH, DH, sA, sB, c);

    const int lane = threadIdx.x & 31;
    const int wm = (threadIdx.x >> 5) & 3, wn = threadIdx.x >> 7;
    #pragma unroll
    for (int i = 0; i < 2; i++) {
        int q = q0 + wm * 32 + i * 16 + (lane >> 2);
        float* row0 = g_s + ((size_t)bh * N_ + q) * N_;
        float* row1 = row0 + 8 * N_;
        #pragma unroll
        for (int j = 0; j < 8; j++) {
            int kk = k0 + wn * 64 + j * 8 + (lane & 3) * 2;
            float2 w0, w1;
            w0.x = c[i][j][0] * 0.125f; w0.y = c[i][j][1] * 0.125f;
            w1.x = c[i][j][2] * 0.125f; w1.y = c[i][j][3] * 0.125f;
            *(float2*)&row0[kk] = w0;
            *(float2*)&row1[kk] = w1;
        }
    }
}

// ---------------- 4) softmax rows of g_s (in place, normalized) ------------
__global__ void softmax_k() {
    const int row = blockIdx.x * 8 + (threadIdx.x >> 5);
    const int lane = threadIdx.x & 31;
    float4* p = (float4*)(g_s + (size_t)row * N_);
    float4 v[8];
    #pragma unroll
    for (int i = 0; i < 8; i++) v[i] = p[lane + 32 * i];
    float mx = -1e30f;
    #pragma unroll
    for (int i = 0; i < 8; i++)
        mx = fmaxf(mx, fmaxf(fmaxf(v[i].x, v[i].y), fmaxf(v[i].z, v[i].w)));
    #pragma unroll
    for (int off = 16; off > 0; off >>= 1)
        mx = fmaxf(mx, __shfl_xor_sync(0xffffffffu, mx, off));
    float sum = 0.f;
    #pragma unroll
    for (int i = 0; i < 8; i++) {
        v[i].x = __expf(v[i].x - mx); v[i].y = __expf(v[i].y - mx);
        v[i].z = __expf(v[i].z - mx); v[i].w = __expf(v[i].w - mx);
        sum += v[i].x + v[i].y + v[i].z + v[i].w;
    }
    #pragma unroll
    for (int off = 16; off > 0; off >>= 1)
        sum += __shfl_xor_sync(0xffffffffu, sum, off);
    const float inv = 1.0f / sum;
    #pragma unroll
    for (int i = 0; i < 8; i++) {
        v[i].x *= inv; v[i].y *= inv; v[i].z *= inv; v[i].w *= inv;
        p[lane + 32 * i] = v[i];
    }
}

// ---------------- 5) O = P V : A=P[q][m] (ld 1024), B=Vt[d][m] (ld 1024) ---
__global__ __launch_bounds__(256) void pv_tc() {
    extern __shared__ float sm[];
    float* sA = sm;
    float* sB = sm + 2 * 128 * PTF;
    const int q0 = blockIdx.x * 128, bh = blockIdx.y;
    float c[2][4][4] = {};
    gemm_tf32<4, 32>(g_s + ((size_t)bh * N_ + q0) * N_, N_,
                     g_vt + (size_t)bh * DH * N_, N_, sA, sB, c);

    const int lane = threadIdx.x & 31;
    const int wm = (threadIdx.x >> 5) & 3, wn = threadIdx.x >> 7;
    const int b = bh >> 2, h = bh & 3;
    #pragma unroll
    for (int i = 0; i < 2; i++) {
        int q = q0 + wm * 32 + i * 16 + (lane >> 2);
        float* row0 = g_ao + ((size_t)(b * N_ + q)) * C_ + h * DH;
        float* row1 = row0 + 8 * C_;
        #pragma unroll
        for (int j = 0; j < 4; j++) {
            int d = wn * 32 + j * 8 + (lane & 3) * 2;
            float2 w0, w1;
            w0.x = c[i][j][0]; w0.y = c[i][j][1];
            w1.x = c[i][j][2]; w1.y = c[i][j][3];
            *(float2*)&row0[d] = w0;
            *(float2*)&row1[d] = w1;
        }
    }
}

// ---------------- 6) proj + bias + residual: D[o][n] -----------------------
__global__ __launch_bounds__(256) void proj_tc(const float* __restrict__ wp,
                                               const float* __restrict__ bias,
                                               const float* __restrict__ x,
                                               float* __restrict__ out) {
    extern __shared__ float sm[];
    float* sA = sm;
    float* sB = sm + 2 * 128 * PTF;
    const int n0 = blockIdx.x * 128, o0 = blockIdx.y * 128, b = blockIdx.z;
    float c[2][8][4] = {};
    gemm_tf32<8, 8>(wp + (size_t)o0 * C_, C_,
                    g_ao + ((size_t)(b * N_ + n0)) * C_, C_, sA, sB, c);

    const int lane = threadIdx.x & 31;
    const int wm = (threadIdx.x >> 5) & 3, wn = threadIdx.x >> 7;
    #pragma unroll
    for (int i = 0; i < 2; i++) {
        int o = o0 + wm * 32 + i * 16 + (lane >> 2);
        float pb0 = bias[o], pb1 = bias[o + 8];
        size_t r0b = ((size_t)(b * C_ + o)) * N_;
        size_t r1b = r0b + 8 * N_;
        #pragma unroll
        for (int j = 0; j < 8; j++) {
            int n = n0 + wn * 64 + j * 8 + (lane & 3) * 2;
            float2 sk0 = *(const float2*)&x[r0b + n];
            float2 sk1 = *(const float2*)&x[r1b + n];
            float2 w0, w1;
            w0.x = c[i][j][0] + pb0 + sk0.x; w0.y = c[i][j][1] + pb0 + sk0.y;
            w1.x = c[i][j][2] + pb1 + sk1.x; w1.y = c[i][j][3] + pb1 + sk1.y;
            *(float2*)&out[r0b + n] = w0;
            *(float2*)&out[r1b + n] = w1;
        }
    }
}

// ---------------------------------------------------------------------------
extern "C" void kernel_launch(void* const* d_in, const int* in_sizes, int n_in,
                              void* d_out, int out_size) {
    const float* x     = (const float*)d_in[0];
    const float* gn_w  = (const float*)d_in[1];
    const float* gn_b  = (const float*)d_in[2];
    const float* qkv_w = (const float*)d_in[3];
    const float* qkv_b = (const float*)d_in[4];
    const float* prj_w = (const float*)d_in[5];
    const float* prj_b = (const float*)d_in[6];
    float* out = (float*)d_out;

    const int smem_main = 2 * (128 + 128) * PTF * 4;   // 73728
    const int smem_pv   = 2 * (128 + 64)  * PTF * 4;   // 55296
    cudaFuncSetAttribute(qkv_tc,  cudaFuncAttributeMaxDynamicSharedMemorySize, smem_main);
    cudaFuncSetAttribute(s_tc,    cudaFuncAttributeMaxDynamicSharedMemorySize, smem_main);
    cudaFuncSetAttribute(pv_tc,   cudaFuncAttributeMaxDynamicSharedMemorySize, smem_pv);
    cudaFuncSetAttribute(proj_tc, cudaFuncAttributeMaxDynamicSharedMemorySize, smem_main);

    gn_kernel<<<B_ * 8, 256>>>(x, gn_w, gn_b);
    qkv_tc<<<dim3(8, 6, B_), 256, smem_main>>>(qkv_w, qkv_b);
    s_tc<<<dim3(8, 8, BH), 256, smem_main>>>();
    softmax_k<<<BH * N_ / 8, 256>>>();
    pv_tc<<<dim3(8, BH), 256, smem_pv>>>();
    proj_tc<<<dim3(8, 2, B_), 256, smem_main>>>(prj_b ? prj_w : prj_w, prj_b, x, out);
}

// round 8
// speedup vs baseline: 3.6797x; 1.2049x over previous
#include <cuda_runtime.h>
#include <math.h>
#include <stdint.h>

#define B_    16
#define C_    256
#define N_    1024
#define HEADS 4
#define DH    64
#define BH    (B_*HEADS)
#define PTF   36        // smem pitch (floats) for 32-wide k tiles (gemm core)
#define PQ    68        // pitch for 64-wide tiles (attn Q/K)
#define PV    132       // pitch for 128-wide tiles (attn P / Vt)

// ---------------- scratch ---------------------------------------------------
__device__ __align__(256) float g_xnt[B_*N_*C_];          // [b][n][c]
__device__ __align__(256) float g_q  [BH*N_*DH];          // [bh][n][d]
__device__ __align__(256) float g_k  [BH*N_*DH];          // [bh][n][d]
__device__ __align__(256) float g_vt [BH*DH*N_];          // [bh][d][m]
__device__ __align__(256) float g_ao [B_*N_*C_];          // [b][n][c]

// ---------------- tf32 mma helpers -----------------------------------------
__device__ __forceinline__ float tf32r(float x) {
    uint32_t o;
    asm("cvt.rna.tf32.f32 %0, %1;" : "=r"(o) : "f"(x));
    return __uint_as_float(o);
}
__device__ __forceinline__ void mma_tf32(float c[4], const float a[4],
                                         float b0, float b1) {
    asm volatile(
        "mma.sync.aligned.m16n8k8.row.col.f32.tf32.tf32.f32 "
        "{%0,%1,%2,%3}, {%4,%5,%6,%7}, {%8,%9}, {%0,%1,%2,%3};"
        : "+f"(c[0]), "+f"(c[1]), "+f"(c[2]), "+f"(c[3])
        : "r"(__float_as_uint(a[0])), "r"(__float_as_uint(a[1])),
          "r"(__float_as_uint(a[2])), "r"(__float_as_uint(a[3])),
          "r"(__float_as_uint(b0)),  "r"(__float_as_uint(b1)));
}
// store logical k8 group [j0..j3 | j4..j7] interleaved: phys = (j<4)?2j:2(j-4)+1
__device__ __forceinline__ void sts_perm(float* srow, int g4,
                                         float4 v0, float4 v1) {
    srow[g4 + 0] = tf32r(v0.x); srow[g4 + 2] = tf32r(v0.y);
    srow[g4 + 4] = tf32r(v0.z); srow[g4 + 6] = tf32r(v0.w);
    srow[g4 + 1] = tf32r(v1.x); srow[g4 + 3] = tf32r(v1.y);
    srow[g4 + 5] = tf32r(v1.z); srow[g4 + 7] = tf32r(v1.w);
}

// CTA 128 x (NJ*16) GEMM (verified R6 core)
template<int NJ, int KT>
__device__ __forceinline__ void gemm_tf32(const float* gA, int lda,
                                          const float* gB, int ldb,
                                          float* sA, float* sB,
                                          float (&c)[2][NJ][4]) {
    const int tid = threadIdx.x, lane = tid & 31;
    const int wm = (tid >> 5) & 3, wn = tid >> 7;
    const int r0 = tid >> 2, g4 = (tid & 3) * 8;
    constexpr int BR   = NJ * 16;
    constexpr int ABUF = 128 * PTF;
    constexpr int BBUF = BR * PTF;

    float4 pa[2][2], pb[BR / 64][2];
    auto ldg = [&](int kt) {
        #pragma unroll
        for (int h = 0; h < 2; h++) {
            pa[0][h] = *(const float4*)(gA + (size_t)r0 * lda + kt * 32 + g4 + h * 4);
            pa[1][h] = *(const float4*)(gA + (size_t)(r0 + 64) * lda + kt * 32 + g4 + h * 4);
            #pragma unroll
            for (int rb = 0; rb < BR / 64; rb++)
                pb[rb][h] = *(const float4*)(gB + (size_t)(r0 + rb * 64) * ldb
                                             + kt * 32 + g4 + h * 4);
        }
    };
    auto sts = [&](int buf) {
        float* dA = sA + buf * ABUF;
        float* dB = sB + buf * BBUF;
        sts_perm(dA + r0 * PTF, g4, pa[0][0], pa[0][1]);
        sts_perm(dA + (r0 + 64) * PTF, g4, pa[1][0], pa[1][1]);
        #pragma unroll
        for (int rb = 0; rb < BR / 64; rb++)
            sts_perm(dB + (r0 + rb * 64) * PTF, g4, pb[rb][0], pb[rb][1]);
    };

    ldg(0); sts(0);
    __syncthreads();
    for (int kt = 0; kt < KT; kt++) {
        const float* cA = sA + (kt & 1) * ABUF;
        const float* cB = sB + (kt & 1) * BBUF;
        if (kt + 1 < KT) ldg(kt + 1);
        #pragma unroll
        for (int g = 0; g < 4; g++) {
            float a[2][4];
            #pragma unroll
            for (int i = 0; i < 2; i++) {
                float2 lo = *(const float2*)&cA[(wm * 32 + i * 16 + (lane >> 2)) * PTF
                                                + g * 8 + 2 * (lane & 3)];
                float2 hi = *(const float2*)&cA[(wm * 32 + i * 16 + 8 + (lane >> 2)) * PTF
                                                + g * 8 + 2 * (lane & 3)];
                a[i][0] = lo.x; a[i][1] = hi.x; a[i][2] = lo.y; a[i][3] = hi.y;
            }
            #pragma unroll
            for (int j = 0; j < NJ; j++) {
                float2 bv = *(const float2*)&cB[(wn * (NJ * 8) + j * 8 + (lane >> 2)) * PTF
                                                + g * 8 + 2 * (lane & 3)];
                #pragma unroll
                for (int i = 0; i < 2; i++)
                    mma_tf32(c[i][j], a[i], bv.x, bv.y);
            }
        }
        if (kt + 1 < KT) sts((kt + 1) & 1);
        __syncthreads();
    }
}

// ---------------- 1) GroupNorm -> fp32 xnt[b][n][c] ------------------------
__global__ void gn_kernel(const float* __restrict__ x,
                          const float* __restrict__ w,
                          const float* __restrict__ bias) {
    const int blk = blockIdx.x;
    const size_t base = (size_t)blk * 32768;
    const int tid = threadIdx.x;

    double s = 0.0, s2 = 0.0;
    for (int i = tid; i < 8192; i += 256) {
        float4 v = *(const float4*)&x[base + i * 4];
        s  += (double)v.x + v.y + v.z + v.w;
        s2 += (double)v.x * v.x + (double)v.y * v.y
            + (double)v.z * v.z + (double)v.w * v.w;
    }
    __shared__ double rs[256], rs2[256];
    rs[tid] = s; rs2[tid] = s2;
    __syncthreads();
    for (int off = 128; off > 0; off >>= 1) {
        if (tid < off) { rs[tid] += rs[tid + off]; rs2[tid] += rs2[tid + off]; }
        __syncthreads();
    }
    __shared__ float smean, sinv;
    if (tid == 0) {
        double mu  = rs[0] * (1.0 / 32768.0);
        double var = rs2[0] * (1.0 / 32768.0) - mu * mu;
        smean = (float)mu;
        sinv  = (float)rsqrt(var + 1e-5);
    }
    __syncthreads();
    const int cbase = (blk & 7) * 32;
    __shared__ float ssc[32], ssb[32];
    if (tid < 32) {
        int cc = cbase + tid;
        float sc = sinv * w[cc];
        ssc[tid] = sc;
        ssb[tid] = bias[cc] - smean * sc;
    }
    __syncthreads();

    __shared__ float tile[128][33];
    const int b = blk >> 3;
    for (int nt = 0; nt < 8; nt++) {
        #pragma unroll
        for (int k2 = 0; k2 < 16; k2++) {
            int idx = tid + k2 * 256;
            int cc = idx >> 7, nn = idx & 127;
            tile[nn][cc] = x[base + (size_t)cc * 1024 + nt * 128 + nn]
                           * ssc[cc] + ssb[cc];
        }
        __syncthreads();
        #pragma unroll
        for (int k2 = 0; k2 < 4; k2++) {
            int idx = tid + k2 * 256;
            int nn = idx >> 3, c4 = (idx & 7) * 4;
            float4 o;
            o.x = tile[nn][c4];     o.y = tile[nn][c4 + 1];
            o.z = tile[nn][c4 + 2]; o.w = tile[nn][c4 + 3];
            *(float4*)&g_xnt[((size_t)(b * N_ + nt * 128 + nn)) * C_ + cbase + c4] = o;
        }
        __syncthreads();
    }
}

// ---------------- 2) QKV: D[n][o] = xnt . Wqkv^T ---------------------------
__global__ __launch_bounds__(256) void qkv_tc(const float* __restrict__ wq,
                                              const float* __restrict__ bias) {
    extern __shared__ float sm[];
    float* sA = sm;
    float* sB = sm + 2 * 128 * PTF;
    const int n0 = blockIdx.x * 128, o0 = blockIdx.y * 128, b = blockIdx.z;
    float c[2][8][4] = {};
    gemm_tf32<8, 8>(g_xnt + ((size_t)(b * N_ + n0)) * C_, C_,
                    wq + (size_t)o0 * C_, C_, sA, sB, c);

    const int lane = threadIdx.x & 31;
    const int wm = (threadIdx.x >> 5) & 3, wn = threadIdx.x >> 7;
    const int t = o0 >> 8;
    const int b4 = b * HEADS;
    #pragma unroll
    for (int i = 0; i < 2; i++) {
        int m = n0 + wm * 32 + i * 16 + (lane >> 2);
        #pragma unroll
        for (int j = 0; j < 8; j++) {
            int o = o0 + wn * 64 + j * 8 + (lane & 3) * 2;
            float b0v = bias[o], b1v = bias[o + 1];
            if (t < 2) {
                float* dst = (t == 0) ? g_q : g_k;
                int h = (o >> 6) & 3, d = o & 63;
                size_t rb = ((size_t)(b4 + h) * N_) * DH + d;
                float2 w0, w1;
                w0.x = c[i][j][0] + b0v; w0.y = c[i][j][1] + b1v;
                w1.x = c[i][j][2] + b0v; w1.y = c[i][j][3] + b1v;
                *(float2*)&dst[rb + (size_t)m * DH] = w0;
                *(float2*)&dst[rb + (size_t)(m + 8) * DH] = w1;
            } else {
                int og = o - 512;
                size_t rb = ((size_t)(b4 + (og >> 6)) * DH + (og & 63)) * N_;
                g_vt[rb + m]            = c[i][j][0] + b0v;
                g_vt[rb + N_ + m]       = c[i][j][1] + b1v;
                g_vt[rb + m + 8]        = c[i][j][2] + b0v;
                g_vt[rb + N_ + m + 8]   = c[i][j][3] + b1v;
            }
        }
    }
}

// ---------------- 3) fused flash attention ---------------------------------
// grid (N_/128, BH), 256 thr / 8 warps (wm 0..3, wn 0..1)
__global__ __launch_bounds__(256) void attn_fused() {
    extern __shared__ float sm[];
    float* sQ  = sm;                       // 128 x PQ
    float* sK  = sQ + 128 * PQ;            // 128 x PQ
    float* sV  = sK + 128 * PQ;            // 64  x PV  (Vt: [d][m])
    float* sP  = sV + 64 * PV;             // 128 x PV
    float* rmx = sP + 128 * PV;            // [2][128]
    float* rsm = rmx + 256;                // [2][128]

    const int tid = threadIdx.x, lane = tid & 31;
    const int wm = (tid >> 5) & 3, wn = tid >> 7;
    const int tq = lane & 3;               // quad col id
    const int q0 = blockIdx.x * 128, bh = blockIdx.y;
    const int b = bh >> 2, hh = bh & 3;

    const float* gQ = g_q + ((size_t)bh * N_ + q0) * DH;
    const float* gK = g_k + (size_t)bh * N_ * DH;
    const float* gV = g_vt + (size_t)bh * DH * N_;

    // load Q tile (128 rows x 64): units (row, g) = 128*8, 4 per thread
    #pragma unroll
    for (int u = 0; u < 4; u++) {
        int idx = u * 256 + tid;
        int row = idx >> 3, g = idx & 7;
        float4 v0 = *(const float4*)(gQ + (size_t)row * DH + g * 8);
        float4 v1 = *(const float4*)(gQ + (size_t)row * DH + g * 8 + 4);
        sts_perm(sQ + row * PQ, g * 8, v0, v1);
    }

    float m_[2][2], l_[2][2], co[2][4][4] = {};
    #pragma unroll
    for (int i = 0; i < 2; i++)
        #pragma unroll
        for (int h = 0; h < 2; h++) { m_[i][h] = -1e30f; l_[i][h] = 0.f; }

    // P store physical offsets for logical cols 2t, 2t+1
    const int p0 = (tq < 2) ? 4 * tq : 4 * tq - 7;
    const int p1 = (tq < 2) ? 4 * tq + 2 : 4 * tq - 5;

    for (int t = 0; t < 8; t++) {
        __syncthreads();   // previous iter's sK/sV/sP/red fully consumed
        // K tile: 128 x 64
        #pragma unroll
        for (int u = 0; u < 4; u++) {
            int idx = u * 256 + tid;
            int row = idx >> 3, g = idx & 7;
            const float* src = gK + (size_t)(t * 128 + row) * DH + g * 8;
            float4 v0 = *(const float4*)(src);
            float4 v1 = *(const float4*)(src + 4);
            sts_perm(sK + row * PQ, g * 8, v0, v1);
        }
        // V tile: Vt 64 x 128 (m-contiguous)
        #pragma unroll
        for (int u = 0; u < 4; u++) {
            int idx = u * 256 + tid;
            int row = idx >> 4, g = idx & 15;
            const float* src = gV + (size_t)row * N_ + t * 128 + g * 8;
            float4 v0 = *(const float4*)(src);
            float4 v1 = *(const float4*)(src + 4);
            sts_perm(sV + row * PV, g * 8, v0, v1);
        }
        __syncthreads();

        // S = Q . K^T (warp tile 32 x 64)
        float cs[2][8][4] = {};
        #pragma unroll
        for (int g = 0; g < 8; g++) {
            float a[2][4];
            #pragma unroll
            for (int i = 0; i < 2; i++) {
                float2 lo = *(const float2*)&sQ[(wm * 32 + i * 16 + (lane >> 2)) * PQ
                                                + g * 8 + 2 * tq];
                float2 hi = *(const float2*)&sQ[(wm * 32 + i * 16 + 8 + (lane >> 2)) * PQ
                                                + g * 8 + 2 * tq];
                a[i][0] = lo.x; a[i][1] = hi.x; a[i][2] = lo.y; a[i][3] = hi.y;
            }
            #pragma unroll
            for (int j = 0; j < 8; j++) {
                float2 bv = *(const float2*)&sK[(wn * 64 + j * 8 + (lane >> 2)) * PQ
                                                + g * 8 + 2 * tq];
                #pragma unroll
                for (int i = 0; i < 2; i++)
                    mma_tf32(cs[i][j], a[i], bv.x, bv.y);
            }
        }

        // row max over this warp's 64 cols -> cross-warp via smem
        #pragma unroll
        for (int i = 0; i < 2; i++)
            #pragma unroll
            for (int h = 0; h < 2; h++) {
                float mx = -1e30f;
                #pragma unroll
                for (int j = 0; j < 8; j++) {
                    cs[i][j][h * 2]     *= 0.125f;
                    cs[i][j][h * 2 + 1] *= 0.125f;
                    mx = fmaxf(mx, fmaxf(cs[i][j][h * 2], cs[i][j][h * 2 + 1]));
                }
                mx = fmaxf(mx, __shfl_xor_sync(0xffffffffu, mx, 1));
                mx = fmaxf(mx, __shfl_xor_sync(0xffffffffu, mx, 2));
                if (tq == 0)
                    rmx[wn * 128 + wm * 32 + i * 16 + h * 8 + (lane >> 2)] = mx;
            }
        __syncthreads();

        // online update + exp + write P + partial sums
        #pragma unroll
        for (int i = 0; i < 2; i++)
            #pragma unroll
            for (int h = 0; h < 2; h++) {
                const int row = wm * 32 + i * 16 + h * 8 + (lane >> 2);
                float nm = fmaxf(m_[i][h], fmaxf(rmx[row], rmx[128 + row]));
                float al = __expf(m_[i][h] - nm);
                m_[i][h] = nm;
                l_[i][h] *= al;
                #pragma unroll
                for (int j = 0; j < 4; j++) {
                    co[i][j][h * 2]     *= al;
                    co[i][j][h * 2 + 1] *= al;
                }
                float ps = 0.f;
                float* prow = sP + row * PV;
                #pragma unroll
                for (int j = 0; j < 8; j++) {
                    float e0 = __expf(cs[i][j][h * 2]     - nm);
                    float e1 = __expf(cs[i][j][h * 2 + 1] - nm);
                    ps += e0 + e1;
                    int gb = (wn * 8 + j) * 8;
                    prow[gb + p0] = tf32r(e0);
                    prow[gb + p1] = tf32r(e1);
                }
                ps += __shfl_xor_sync(0xffffffffu, ps, 1);
                ps += __shfl_xor_sync(0xffffffffu, ps, 2);
                if (tq == 0) rsm[wn * 128 + row] = ps;
            }
        __syncthreads();

        #pragma unroll
        for (int i = 0; i < 2; i++)
            #pragma unroll
            for (int h = 0; h < 2; h++) {
                const int row = wm * 32 + i * 16 + h * 8 + (lane >> 2);
                l_[i][h] += rsm[row] + rsm[128 + row];
            }

        // O += P . V (warp tile 32 x 32, k = 128)
        #pragma unroll
        for (int g = 0; g < 16; g++) {
            float a[2][4];
            #pragma unroll
            for (int i = 0; i < 2; i++) {
                float2 lo = *(const float2*)&sP[(wm * 32 + i * 16 + (lane >> 2)) * PV
                                                + g * 8 + 2 * tq];
                float2 hi = *(const float2*)&sP[(wm * 32 + i * 16 + 8 + (lane >> 2)) * PV
                                                + g * 8 + 2 * tq];
                a[i][0] = lo.x; a[i][1] = hi.x; a[i][2] = lo.y; a[i][3] = hi.y;
            }
            #pragma unroll
            for (int j = 0; j < 4; j++) {
                float2 bv = *(const float2*)&sV[(wn * 32 + j * 8 + (lane >> 2)) * PV
                                                + g * 8 + 2 * tq];
                #pragma unroll
                for (int i = 0; i < 2; i++)
                    mma_tf32(co[i][j], a[i], bv.x, bv.y);
            }
        }
    }

    // epilogue: normalize + write g_ao[b][n][c]
    #pragma unroll
    for (int i = 0; i < 2; i++)
        #pragma unroll
        for (int h = 0; h < 2; h++) {
            const int q = q0 + wm * 32 + i * 16 + h * 8 + (lane >> 2);
            const float inv = 1.0f / l_[i][h];
            float* row = g_ao + ((size_t)(b * N_ + q)) * C_ + hh * DH;
            #pragma unroll
            for (int j = 0; j < 4; j++) {
                int d = wn * 32 + j * 8 + 2 * tq;
                float2 w;
                w.x = co[i][j][h * 2] * inv;
                w.y = co[i][j][h * 2 + 1] * inv;
                *(float2*)&row[d] = w;
            }
        }
}

// ---------------- 4) proj + bias + residual: D[o][n] -----------------------
__global__ __launch_bounds__(256) void proj_tc(const float* __restrict__ wp,
                                               const float* __restrict__ bias,
                                               const float* __restrict__ x,
                                               float* __restrict__ out) {
    extern __shared__ float sm[];
    float* sA = sm;
    float* sB = sm + 2 * 128 * PTF;
    const int n0 = blockIdx.x * 128, o0 = blockIdx.y * 128, b = blockIdx.z;
    float c[2][8][4] = {};
    gemm_tf32<8, 8>(wp + (size_t)o0 * C_, C_,
                    g_ao + ((size_t)(b * N_ + n0)) * C_, C_, sA, sB, c);

    const int lane = threadIdx.x & 31;
    const int wm = (threadIdx.x >> 5) & 3, wn = threadIdx.x >> 7;
    #pragma unroll
    for (int i = 0; i < 2; i++) {
        int o = o0 + wm * 32 + i * 16 + (lane >> 2);
        float pb0 = bias[o], pb1 = bias[o + 8];
        size_t r0b = ((size_t)(b * C_ + o)) * N_;
        size_t r1b = r0b + 8 * N_;
        #pragma unroll
        for (int j = 0; j < 8; j++) {
            int n = n0 + wn * 64 + j * 8 + (lane & 3) * 2;
            float2 sk0 = *(const float2*)&x[r0b + n];
            float2 sk1 = *(const float2*)&x[r1b + n];
            float2 w0, w1;
            w0.x = c[i][j][0] + pb0 + sk0.x; w0.y = c[i][j][1] + pb0 + sk0.y;
            w1.x = c[i][j][2] + pb1 + sk1.x; w1.y = c[i][j][3] + pb1 + sk1.y;
            *(float2*)&out[r0b + n] = w0;
            *(float2*)&out[r1b + n] = w1;
        }
    }
}

// ---------------------------------------------------------------------------
extern "C" void kernel_launch(void* const* d_in, const int* in_sizes, int n_in,
                              void* d_out, int out_size) {
    const float* x     = (const float*)d_in[0];
    const float* gn_w  = (const float*)d_in[1];
    const float* gn_b  = (const float*)d_in[2];
    const float* qkv_w = (const float*)d_in[3];
    const float* qkv_b = (const float*)d_in[4];
    const float* prj_w = (const float*)d_in[5];
    const float* prj_b = (const float*)d_in[6];
    float* out = (float*)d_out;

    const int smem_main = 2 * (128 + 128) * PTF * 4;                 // 73728
    const int smem_attn = (128 * PQ + 128 * PQ + 64 * PV + 128 * PV
                           + 512) * 4;                               // ~175KB
    cudaFuncSetAttribute(qkv_tc,     cudaFuncAttributeMaxDynamicSharedMemorySize, smem_main);
    cudaFuncSetAttribute(attn_fused, cudaFuncAttributeMaxDynamicSharedMemorySize, smem_attn);
    cudaFuncSetAttribute(proj_tc,    cudaFuncAttributeMaxDynamicSharedMemorySize, smem_main);

    gn_kernel<<<B_ * 8, 256>>>(x, gn_w, gn_b);
    qkv_tc<<<dim3(8, 6, B_), 256, smem_main>>>(qkv_w, qkv_b);
    attn_fused<<<dim3(8, BH), 256, smem_attn>>>();
    proj_tc<<<dim3(8, 2, B_), 256, smem_main>>>(prj_w, prj_b, x, out);
}

// round 9
// speedup vs baseline: 3.7460x; 1.0180x over previous
#include <cuda_runtime.h>
#include <math.h>
#include <stdint.h>

#define B_    16
#define C_    256
#define N_    1024
#define HEADS 4
#define DH    64
#define BH    (B_*HEADS)
#define PTF   36        // smem pitch (floats) for 32-wide k tiles (gemm core)
#define PQ    68        // pitch for 64-wide tiles (attn K)
#define PV    132       // pitch for 128-wide tiles (attn Vt)

// ---------------- scratch ---------------------------------------------------
__device__ __align__(256) float g_xnt[B_*N_*C_];          // [b][n][c]
__device__ __align__(256) float g_q  [BH*N_*DH];          // [bh][n][d]
__device__ __align__(256) float g_k  [BH*N_*DH];          // [bh][n][d]
__device__ __align__(256) float g_vt [BH*DH*N_];          // [bh][d][m]
__device__ __align__(256) float g_ao [B_*N_*C_];          // [b][n][c]

// ---------------- tf32 mma helpers -----------------------------------------
__device__ __forceinline__ float tf32r(float x) {
    uint32_t o;
    asm("cvt.rna.tf32.f32 %0, %1;" : "=r"(o) : "f"(x));
    return __uint_as_float(o);
}
__device__ __forceinline__ void mma_tf32(float c[4], const float a[4],
                                         float b0, float b1) {
    asm volatile(
        "mma.sync.aligned.m16n8k8.row.col.f32.tf32.tf32.f32 "
        "{%0,%1,%2,%3}, {%4,%5,%6,%7}, {%8,%9}, {%0,%1,%2,%3};"
        : "+f"(c[0]), "+f"(c[1]), "+f"(c[2]), "+f"(c[3])
        : "r"(__float_as_uint(a[0])), "r"(__float_as_uint(a[1])),
          "r"(__float_as_uint(a[2])), "r"(__float_as_uint(a[3])),
          "r"(__float_as_uint(b0)),  "r"(__float_as_uint(b1)));
}
// store logical k8 group [j0..j3 | j4..j7] interleaved: phys = (j<4)?2j:2(j-4)+1
__device__ __forceinline__ void sts_perm(float* srow, int g4,
                                         float4 v0, float4 v1) {
    srow[g4 + 0] = tf32r(v0.x); srow[g4 + 2] = tf32r(v0.y);
    srow[g4 + 4] = tf32r(v0.z); srow[g4 + 6] = tf32r(v0.w);
    srow[g4 + 1] = tf32r(v1.x); srow[g4 + 3] = tf32r(v1.y);
    srow[g4 + 5] = tf32r(v1.z); srow[g4 + 7] = tf32r(v1.w);
}

// CTA 128 x (NJ*16) GEMM (verified R6 core)
template<int NJ, int KT>
__device__ __forceinline__ void gemm_tf32(const float* gA, int lda,
                                          const float* gB, int ldb,
                                          float* sA, float* sB,
                                          float (&c)[2][NJ][4]) {
    const int tid = threadIdx.x, lane = tid & 31;
    const int wm = (tid >> 5) & 3, wn = tid >> 7;
    const int r0 = tid >> 2, g4 = (tid & 3) * 8;
    constexpr int BR   = NJ * 16;
    constexpr int ABUF = 128 * PTF;
    constexpr int BBUF = BR * PTF;

    float4 pa[2][2], pb[BR / 64][2];
    auto ldg = [&](int kt) {
        #pragma unroll
        for (int h = 0; h < 2; h++) {
            pa[0][h] = *(const float4*)(gA + (size_t)r0 * lda + kt * 32 + g4 + h * 4);
            pa[1][h] = *(const float4*)(gA + (size_t)(r0 + 64) * lda + kt * 32 + g4 + h * 4);
            #pragma unroll
            for (int rb = 0; rb < BR / 64; rb++)
                pb[rb][h] = *(const float4*)(gB + (size_t)(r0 + rb * 64) * ldb
                                             + kt * 32 + g4 + h * 4);
        }
    };
    auto sts = [&](int buf) {
        float* dA = sA + buf * ABUF;
        float* dB = sB + buf * BBUF;
        sts_perm(dA + r0 * PTF, g4, pa[0][0], pa[0][1]);
        sts_perm(dA + (r0 + 64) * PTF, g4, pa[1][0], pa[1][1]);
        #pragma unroll
        for (int rb = 0; rb < BR / 64; rb++)
            sts_perm(dB + (r0 + rb * 64) * PTF, g4, pb[rb][0], pb[rb][1]);
    };

    ldg(0); sts(0);
    __syncthreads();
    for (int kt = 0; kt < KT; kt++) {
        const float* cA = sA + (kt & 1) * ABUF;
        const float* cB = sB + (kt & 1) * BBUF;
        if (kt + 1 < KT) ldg(kt + 1);
        #pragma unroll
        for (int g = 0; g < 4; g++) {
            float a[2][4];
            #pragma unroll
            for (int i = 0; i < 2; i++) {
                float2 lo = *(const float2*)&cA[(wm * 32 + i * 16 + (lane >> 2)) * PTF
                                                + g * 8 + 2 * (lane & 3)];
                float2 hi = *(const float2*)&cA[(wm * 32 + i * 16 + 8 + (lane >> 2)) * PTF
                                                + g * 8 + 2 * (lane & 3)];
                a[i][0] = lo.x; a[i][1] = hi.x; a[i][2] = lo.y; a[i][3] = hi.y;
            }
            #pragma unroll
            for (int j = 0; j < NJ; j++) {
                float2 bv = *(const float2*)&cB[(wn * (NJ * 8) + j * 8 + (lane >> 2)) * PTF
                                                + g * 8 + 2 * (lane & 3)];
                #pragma unroll
                for (int i = 0; i < 2; i++)
                    mma_tf32(c[i][j], a[i], bv.x, bv.y);
            }
        }
        if (kt + 1 < KT) sts((kt + 1) & 1);
        __syncthreads();
    }
}

// ---------------- 1) GroupNorm -> fp32 xnt[b][n][c] ------------------------
__global__ void gn_kernel(const float* __restrict__ x,
                          const float* __restrict__ w,
                          const float* __restrict__ bias) {
    const int blk = blockIdx.x;
    const size_t base = (size_t)blk * 32768;
    const int tid = threadIdx.x;

    double s = 0.0, s2 = 0.0;
    for (int i = tid; i < 8192; i += 256) {
        float4 v = *(const float4*)&x[base + i * 4];
        s  += (double)v.x + v.y + v.z + v.w;
        s2 += (double)v.x * v.x + (double)v.y * v.y
            + (double)v.z * v.z + (double)v.w * v.w;
    }
    __shared__ double rs[256], rs2[256];
    rs[tid] = s; rs2[tid] = s2;
    __syncthreads();
    for (int off = 128; off > 0; off >>= 1) {
        if (tid < off) { rs[tid] += rs[tid + off]; rs2[tid] += rs2[tid + off]; }
        __syncthreads();
    }
    __shared__ float smean, sinv;
    if (tid == 0) {
        double mu  = rs[0] * (1.0 / 32768.0);
        double var = rs2[0] * (1.0 / 32768.0) - mu * mu;
        smean = (float)mu;
        sinv  = (float)rsqrt(var + 1e-5);
    }
    __syncthreads();
    const int cbase = (blk & 7) * 32;
    __shared__ float ssc[32], ssb[32];
    if (tid < 32) {
        int cc = cbase + tid;
        float sc = sinv * w[cc];
        ssc[tid] = sc;
        ssb[tid] = bias[cc] - smean * sc;
    }
    __syncthreads();

    __shared__ float tile[128][33];
    const int b = blk >> 3;
    for (int nt = 0; nt < 8; nt++) {
        #pragma unroll
        for (int k2 = 0; k2 < 16; k2++) {
            int idx = tid + k2 * 256;
            int cc = idx >> 7, nn = idx & 127;
            tile[nn][cc] = x[base + (size_t)cc * 1024 + nt * 128 + nn]
                           * ssc[cc] + ssb[cc];
        }
        __syncthreads();
        #pragma unroll
        for (int k2 = 0; k2 < 4; k2++) {
            int idx = tid + k2 * 256;
            int nn = idx >> 3, c4 = (idx & 7) * 4;
            float4 o;
            o.x = tile[nn][c4];     o.y = tile[nn][c4 + 1];
            o.z = tile[nn][c4 + 2]; o.w = tile[nn][c4 + 3];
            *(float4*)&g_xnt[((size_t)(b * N_ + nt * 128 + nn)) * C_ + cbase + c4] = o;
        }
        __syncthreads();
    }
}

// ---------------- 2) QKV: D[n][o] = xnt . Wqkv^T ---------------------------
__global__ __launch_bounds__(256) void qkv_tc(const float* __restrict__ wq,
                                              const float* __restrict__ bias) {
    extern __shared__ float sm[];
    float* sA = sm;
    float* sB = sm + 2 * 128 * PTF;
    const int n0 = blockIdx.x * 128, o0 = blockIdx.y * 128, b = blockIdx.z;
    float c[2][8][4] = {};
    gemm_tf32<8, 8>(g_xnt + ((size_t)(b * N_ + n0)) * C_, C_,
                    wq + (size_t)o0 * C_, C_, sA, sB, c);

    const int lane = threadIdx.x & 31;
    const int wm = (threadIdx.x >> 5) & 3, wn = threadIdx.x >> 7;
    const int t = o0 >> 8;
    const int b4 = b * HEADS;
    #pragma unroll
    for (int i = 0; i < 2; i++) {
        int m = n0 + wm * 32 + i * 16 + (lane >> 2);
        #pragma unroll
        for (int j = 0; j < 8; j++) {
            int o = o0 + wn * 64 + j * 8 + (lane & 3) * 2;
            float b0v = bias[o], b1v = bias[o + 1];
            if (t < 2) {
                float* dst = (t == 0) ? g_q : g_k;
                int h = (o >> 6) & 3, d = o & 63;
                size_t rb = ((size_t)(b4 + h) * N_) * DH + d;
                float2 w0, w1;
                w0.x = c[i][j][0] + b0v; w0.y = c[i][j][1] + b1v;
                w1.x = c[i][j][2] + b0v; w1.y = c[i][j][3] + b1v;
                *(float2*)&dst[rb + (size_t)m * DH] = w0;
                *(float2*)&dst[rb + (size_t)(m + 8) * DH] = w1;
            } else {
                int og = o - 512;
                size_t rb = ((size_t)(b4 + (og >> 6)) * DH + (og & 63)) * N_;
                g_vt[rb + m]            = c[i][j][0] + b0v;
                g_vt[rb + N_ + m]       = c[i][j][1] + b1v;
                g_vt[rb + m + 8]        = c[i][j][2] + b0v;
                g_vt[rb + N_ + m + 8]   = c[i][j][3] + b1v;
            }
        }
    }
}

// ---------------- 3) fused flash attention, warp-private softmax -----------
// grid (N_/128, BH), 256 thr / 8 warps; warp w owns q rows [w*16, w*16+16)
__global__ __launch_bounds__(256) void attn_fused() {
    extern __shared__ float sm[];
    float* sK = sm;                        // 2 x 128 x PQ  (K: [m][d])
    float* sV = sm + 2 * 128 * PQ;         // 2 x 64 x PV   (Vt: [d][m])

    const int tid = threadIdx.x, lane = tid & 31;
    const int wid = tid >> 5;
    const int tq = lane & 3, rq = lane >> 2;
    const int q0 = blockIdx.x * 128, bh = blockIdx.y;
    const int b = bh >> 2, hh = bh & 3;

    const float* gQ = g_q + ((size_t)bh * N_ + q0) * DH;
    const float* gK = g_k + (size_t)bh * N_ * DH;
    const float* gV = g_vt + (size_t)bh * DH * N_;

    // Q fragments in registers, pre-scaled by 1/8 (exact power of 2)
    float aq[8][4];
    {
        const float* q_r0 = gQ + (size_t)(wid * 16 + rq) * DH;
        const float* q_r1 = q_r0 + 8 * DH;
        #pragma unroll
        for (int g = 0; g < 8; g++) {
            aq[g][0] = tf32r(0.125f * q_r0[g * 8 + tq]);
            aq[g][1] = tf32r(0.125f * q_r1[g * 8 + tq]);
            aq[g][2] = tf32r(0.125f * q_r0[g * 8 + tq + 4]);
            aq[g][3] = tf32r(0.125f * q_r1[g * 8 + tq + 4]);
        }
    }

    float m0 = -1e30f, m1 = -1e30f, l0 = 0.f, l1 = 0.f;
    float co[8][4] = {};

    float4 pk[4][2], pv[4][2];
    auto ldg = [&](int t) {
        #pragma unroll
        for (int u = 0; u < 4; u++) {
            int idx = u * 256 + tid;
            {   int row = idx >> 3, g = idx & 7;
                const float* src = gK + (size_t)(t * 128 + row) * DH + g * 8;
                pk[u][0] = *(const float4*)src;
                pk[u][1] = *(const float4*)(src + 4); }
            {   int row = idx >> 4, g = idx & 15;
                const float* src = gV + (size_t)row * N_ + t * 128 + g * 8;
                pv[u][0] = *(const float4*)src;
                pv[u][1] = *(const float4*)(src + 4); }
        }
    };
    auto sts = [&](int buf) {
        float* dK = sK + buf * 128 * PQ;
        float* dV = sV + buf * 64 * PV;
        #pragma unroll
        for (int u = 0; u < 4; u++) {
            int idx = u * 256 + tid;
            {   int row = idx >> 3, g = idx & 7;
                sts_perm(dK + row * PQ, g * 8, pk[u][0], pk[u][1]); }
            {   int row = idx >> 4, g = idx & 15;
                sts_perm(dV + row * PV, g * 8, pv[u][0], pv[u][1]); }
        }
    };

    ldg(0); sts(0);
    __syncthreads();

    const int s0l = (lane & ~3) | (tq >> 1);    // shfl src for cols t
    const int s1l = s0l + 2;                    // shfl src for cols t+4
    const bool odd = tq & 1;

    for (int t = 0; t < 8; t++) {
        if (t < 7) ldg(t + 1);
        const float* cK = sK + (t & 1) * 128 * PQ;
        const float* cV = sV + (t & 1) * 64 * PV;

        // ---- S = (Q/8) . K^T : warp tile 16 x 128 ----
        float cs[16][4] = {};
        #pragma unroll
        for (int g = 0; g < 8; g++) {
            #pragma unroll
            for (int j = 0; j < 16; j++) {
                float2 bv = *(const float2*)&cK[(j * 8 + rq) * PQ + g * 8 + 2 * tq];
                mma_tf32(cs[j], aq[g], bv.x, bv.y);
            }
        }

        // ---- warp-private online softmax ----
        float mx0 = -1e30f, mx1 = -1e30f;
        #pragma unroll
        for (int j = 0; j < 16; j++) {
            mx0 = fmaxf(mx0, fmaxf(cs[j][0], cs[j][1]));
            mx1 = fmaxf(mx1, fmaxf(cs[j][2], cs[j][3]));
        }
        mx0 = fmaxf(mx0, __shfl_xor_sync(0xffffffffu, mx0, 1));
        mx0 = fmaxf(mx0, __shfl_xor_sync(0xffffffffu, mx0, 2));
        mx1 = fmaxf(mx1, __shfl_xor_sync(0xffffffffu, mx1, 1));
        mx1 = fmaxf(mx1, __shfl_xor_sync(0xffffffffu, mx1, 2));
        float nm0 = fmaxf(m0, mx0), nm1 = fmaxf(m1, mx1);
        float al0 = __expf(m0 - nm0), al1 = __expf(m1 - nm1);
        m0 = nm0; m1 = nm1;
        float ps0 = 0.f, ps1 = 0.f;
        #pragma unroll
        for (int j = 0; j < 16; j++) {
            cs[j][0] = __expf(cs[j][0] - nm0);
            cs[j][1] = __expf(cs[j][1] - nm0);
            cs[j][2] = __expf(cs[j][2] - nm1);
            cs[j][3] = __expf(cs[j][3] - nm1);
            ps0 += cs[j][0] + cs[j][1];
            ps1 += cs[j][2] + cs[j][3];
        }
        ps0 += __shfl_xor_sync(0xffffffffu, ps0, 1);
        ps0 += __shfl_xor_sync(0xffffffffu, ps0, 2);
        ps1 += __shfl_xor_sync(0xffffffffu, ps1, 1);
        ps1 += __shfl_xor_sync(0xffffffffu, ps1, 2);
        l0 = l0 * al0 + ps0;
        l1 = l1 * al1 + ps1;
        #pragma unroll
        for (int jd = 0; jd < 8; jd++) {
            co[jd][0] *= al0; co[jd][1] *= al0;
            co[jd][2] *= al1; co[jd][3] *= al1;
        }

        // ---- C-frag -> A-frag permutation (quad shuffles), in place ----
        #pragma unroll
        for (int j = 0; j < 16; j++) {
            float e0 = __shfl_sync(0xffffffffu, cs[j][0], s0l);
            float o0 = __shfl_sync(0xffffffffu, cs[j][1], s0l);
            float e1 = __shfl_sync(0xffffffffu, cs[j][0], s1l);
            float o1 = __shfl_sync(0xffffffffu, cs[j][1], s1l);
            float e2 = __shfl_sync(0xffffffffu, cs[j][2], s0l);
            float o2 = __shfl_sync(0xffffffffu, cs[j][3], s0l);
            float e3 = __shfl_sync(0xffffffffu, cs[j][2], s1l);
            float o3 = __shfl_sync(0xffffffffu, cs[j][3], s1l);
            cs[j][0] = tf32r(odd ? o0 : e0);
            cs[j][2] = tf32r(odd ? o1 : e1);
            cs[j][1] = tf32r(odd ? o2 : e2);
            cs[j][3] = tf32r(odd ? o3 : e3);
        }

        // ---- O += P . V : warp tile 16 x 64, k = 128 ----
        #pragma unroll
        for (int j = 0; j < 16; j++) {
            #pragma unroll
            for (int jd = 0; jd < 8; jd++) {
                float2 bv = *(const float2*)&cV[(jd * 8 + rq) * PV + j * 8 + 2 * tq];
                mma_tf32(co[jd], cs[j], bv.x, bv.y);
            }
        }

        if (t < 7) { sts((t + 1) & 1); __syncthreads(); }
    }

    // ---- epilogue: normalize + write g_ao[b][n][c] ----
    const float inv0 = 1.0f / l0, inv1 = 1.0f / l1;
    const int qrow = q0 + wid * 16 + rq;
    float* row0 = g_ao + ((size_t)(b * N_ + qrow)) * C_ + hh * DH;
    float* row1 = row0 + 8 * C_;
    #pragma unroll
    for (int jd = 0; jd < 8; jd++) {
        int d = jd * 8 + 2 * tq;
        float2 w0, w1;
        w0.x = co[jd][0] * inv0; w0.y = co[jd][1] * inv0;
        w1.x = co[jd][2] * inv1; w1.y = co[jd][3] * inv1;
        *(float2*)&row0[d] = w0;
        *(float2*)&row1[d] = w1;
    }
}

// ---------------- 4) proj + bias + residual: D[o][n] -----------------------
__global__ __launch_bounds__(256) void proj_tc(const float* __restrict__ wp,
                                               const float* __restrict__ bias,
                                               const float* __restrict__ x,
                                               float* __restrict__ out) {
    extern __shared__ float sm[];
    float* sA = sm;
    float* sB = sm + 2 * 128 * PTF;
    const int n0 = blockIdx.x * 128, o0 = blockIdx.y * 128, b = blockIdx.z;
    float c[2][8][4] = {};
    gemm_tf32<8, 8>(wp + (size_t)o0 * C_, C_,
                    g_ao + ((size_t)(b * N_ + n0)) * C_, C_, sA, sB, c);

    const int lane = threadIdx.x & 31;
    const int wm = (threadIdx.x >> 5) & 3, wn = threadIdx.x >> 7;
    #pragma unroll
    for (int i = 0; i < 2; i++) {
        int o = o0 + wm * 32 + i * 16 + (lane >> 2);
        float pb0 = bias[o], pb1 = bias[o + 8];
        size_t r0b = ((size_t)(b * C_ + o)) * N_;
        size_t r1b = r0b + 8 * N_;
        #pragma unroll
        for (int j = 0; j < 8; j++) {
            int n = n0 + wn * 64 + j * 8 + (lane & 3) * 2;
            float2 sk0 = *(const float2*)&x[r0b + n];
            float2 sk1 = *(const float2*)&x[r1b + n];
            float2 w0, w1;
            w0.x = c[i][j][0] + pb0 + sk0.x; w0.y = c[i][j][1] + pb0 + sk0.y;
            w1.x = c[i][j][2] + pb1 + sk1.x; w1.y = c[i][j][3] + pb1 + sk1.y;
            *(float2*)&out[r0b + n] = w0;
            *(float2*)&out[r1b + n] = w1;
        }
    }
}

// ---------------------------------------------------------------------------
extern "C" void kernel_launch(void* const* d_in, const int* in_sizes, int n_in,
                              void* d_out, int out_size) {
    const float* x     = (const float*)d_in[0];
    const float* gn_w  = (const float*)d_in[1];
    const float* gn_b  = (const float*)d_in[2];
    const float* qkv_w = (const float*)d_in[3];
    const float* qkv_b = (const float*)d_in[4];
    const float* prj_w = (const float*)d_in[5];
    const float* prj_b = (const float*)d_in[6];
    float* out = (float*)d_out;

    const int smem_main = 2 * (128 + 128) * PTF * 4;          // 73728
    const int smem_attn = (2 * 128 * PQ + 2 * 64 * PV) * 4;   // 137216
    cudaFuncSetAttribute(qkv_tc,     cudaFuncAttributeMaxDynamicSharedMemorySize, smem_main);
    cudaFuncSetAttribute(attn_fused, cudaFuncAttributeMaxDynamicSharedMemorySize, smem_attn);
    cudaFuncSetAttribute(proj_tc,    cudaFuncAttributeMaxDynamicSharedMemorySize, smem_main);

    gn_kernel<<<B_ * 8, 256>>>(x, gn_w, gn_b);
    qkv_tc<<<dim3(8, 6, B_), 256, smem_main>>>(qkv_w, qkv_b);
    attn_fused<<<dim3(8, BH), 256, smem_attn>>>();
    proj_tc<<<dim3(8, 2, B_), 256, smem_main>>>(prj_w, prj_b, x, out);
}

// round 10
// speedup vs baseline: 4.8768x; 1.3019x over previous
#include <cuda_runtime.h>
#include <math.h>
#include <stdint.h>

#define B_    16
#define C_    256
#define N_    1024
#define HEADS 4
#define DH    64
#define BH    (B_*HEADS)
#define PTF   36        // smem pitch (floats), 32-wide k panels (gemm core)
#define PA    68        // smem pitch (floats), 64-wide panels (attn)

// ---------------- scratch ---------------------------------------------------
__device__ __align__(256) float g_xnt[B_*N_*C_];          // [b][n][c]
__device__ __align__(256) float g_q  [BH*N_*DH];          // [bh][n][d]
__device__ __align__(256) float g_k  [BH*N_*DH];          // [bh][n][d]
__device__ __align__(256) float g_vt [BH*DH*N_];          // [bh][d][m]
__device__ __align__(256) float g_ao [B_*N_*C_];          // [b][n][c]

// ---------------- helpers ---------------------------------------------------
__device__ __forceinline__ uint32_t su32(const void* p) {
    uint32_t r;
    asm("{ .reg .u64 t; cvta.to.shared.u64 t, %1; cvt.u32.u64 %0, t; }"
        : "=r"(r) : "l"(p));
    return r;
}
__device__ __forceinline__ float tf32r(float x) {
    uint32_t o;
    asm("cvt.rna.tf32.f32 %0, %1;" : "=r"(o) : "f"(x));
    return __uint_as_float(o);
}
__device__ __forceinline__ float ex2f(float x) {
    float r;
    asm("ex2.approx.f32 %0, %1;" : "=f"(r) : "f"(x));
    return r;
}
__device__ __forceinline__ void mma_tf32(float c[4], const float a[4],
                                         float b0, float b1) {
    asm volatile(
        "mma.sync.aligned.m16n8k8.row.col.f32.tf32.tf32.f32 "
        "{%0,%1,%2,%3}, {%4,%5,%6,%7}, {%8,%9}, {%0,%1,%2,%3};"
        : "+f"(c[0]), "+f"(c[1]), "+f"(c[2]), "+f"(c[3])
        : "r"(__float_as_uint(a[0])), "r"(__float_as_uint(a[1])),
          "r"(__float_as_uint(a[2])), "r"(__float_as_uint(a[3])),
          "r"(__float_as_uint(b0)),  "r"(__float_as_uint(b1)));
}
__device__ __forceinline__ void cpa16(uint32_t s, const void* g) {
    asm volatile("cp.async.ca.shared.global [%0], [%1], 16;"
                 :: "r"(s), "l"(g) : "memory");
}
#define CP_COMMIT() asm volatile("cp.async.commit_group;" ::: "memory")
#define CP_WAIT(n)  asm volatile("cp.async.wait_group %0;" :: "n"(n) : "memory")

// ---- 128x128 GEMM core: C = A(128xK,lda) . B(128xK,ldb)^T, 3-stage cp.async
// 256 thr / 8 warps (4m x 2n), BK=32, plain layout pitch PTF.
template<int KT>
__device__ __forceinline__ void gemm_cp(const float* gA, int lda,
                                        const float* gB, int ldb,
                                        float* sA, float* sB,
                                        float (&c)[2][8][4]) {
    const int tid = threadIdx.x, lane = tid & 31;
    const int wm = (tid >> 5) & 3, wn = tid >> 7;
    const int tq = lane & 3, rq = lane >> 2;
    constexpr int BUF = 128 * PTF;
    const uint32_t suA = su32(sA), suB = su32(sB);

    auto ldg = [&](int kt, int st) {
        const uint32_t dA = suA + st * BUF * 4;
        const uint32_t dB = suB + st * BUF * 4;
        #pragma unroll
        for (int u = 0; u < 4; u++) {
            int unit = u * 256 + tid;
            int row = unit >> 3, cc = (unit & 7) * 4;
            cpa16(dA + (row * PTF + cc) * 4, gA + (size_t)row * lda + kt * 32 + cc);
            cpa16(dB + (row * PTF + cc) * 4, gB + (size_t)row * ldb + kt * 32 + cc);
        }
    };

    ldg(0, 0); CP_COMMIT();
    if (KT > 1) ldg(1, 1);
    CP_COMMIT();

    for (int kt = 0; kt < KT; kt++) {
        CP_WAIT(1);
        __syncthreads();
        if (kt + 2 < KT) ldg(kt + 2, (kt + 2) % 3);
        CP_COMMIT();
        const float* cA = sA + (kt % 3) * BUF;
        const float* cB = sB + (kt % 3) * BUF;
        #pragma unroll
        for (int g = 0; g < 4; g++) {
            float a[2][4];
            #pragma unroll
            for (int i = 0; i < 2; i++) {
                const float* ar = cA + (wm * 32 + i * 16 + rq) * PTF + g * 8 + tq;
                a[i][0] = ar[0];
                a[i][1] = ar[8 * PTF];
                a[i][2] = ar[4];
                a[i][3] = ar[8 * PTF + 4];
            }
            #pragma unroll
            for (int j = 0; j < 8; j++) {
                const float* br = cB + (wn * 64 + j * 8 + rq) * PTF + g * 8 + tq;
                #pragma unroll
                for (int i = 0; i < 2; i++)
                    mma_tf32(c[i][j], a[i], br[0], br[4]);
            }
        }
        __syncthreads();
    }
}

// ---------------- 1) GroupNorm -> fp32 xnt[b][n][c] ------------------------
__global__ void gn_kernel(const float* __restrict__ x,
                          const float* __restrict__ w,
                          const float* __restrict__ bias) {
    const int blk = blockIdx.x;
    const size_t base = (size_t)blk * 32768;
    const int tid = threadIdx.x;

    double s = 0.0, s2 = 0.0;
    for (int i = tid; i < 8192; i += 256) {
        float4 v = *(const float4*)&x[base + i * 4];
        s  += (double)v.x + v.y + v.z + v.w;
        s2 += (double)v.x * v.x + (double)v.y * v.y
            + (double)v.z * v.z + (double)v.w * v.w;
    }
    __shared__ double rs[256], rs2[256];
    rs[tid] = s; rs2[tid] = s2;
    __syncthreads();
    for (int off = 128; off > 0; off >>= 1) {
        if (tid < off) { rs[tid] += rs[tid + off]; rs2[tid] += rs2[tid + off]; }
        __syncthreads();
    }
    __shared__ float smean, sinv;
    if (tid == 0) {
        double mu  = rs[0] * (1.0 / 32768.0);
        double var = rs2[0] * (1.0 / 32768.0) - mu * mu;
        smean = (float)mu;
        sinv  = (float)rsqrt(var + 1e-5);
    }
    __syncthreads();
    const int cbase = (blk & 7) * 32;
    __shared__ float ssc[32], ssb[32];
    if (tid < 32) {
        int cc = cbase + tid;
        float sc = sinv * w[cc];
        ssc[tid] = sc;
        ssb[tid] = bias[cc] - smean * sc;
    }
    __syncthreads();

    __shared__ float tile[128][33];
    const int b = blk >> 3;
    for (int nt = 0; nt < 8; nt++) {
        #pragma unroll
        for (int k2 = 0; k2 < 16; k2++) {
            int idx = tid + k2 * 256;
            int cc = idx >> 7, nn = idx & 127;
            tile[nn][cc] = x[base + (size_t)cc * 1024 + nt * 128 + nn]
                           * ssc[cc] + ssb[cc];
        }
        __syncthreads();
        #pragma unroll
        for (int k2 = 0; k2 < 4; k2++) {
            int idx = tid + k2 * 256;
            int nn = idx >> 3, c4 = (idx & 7) * 4;
            float4 o;
            o.x = tile[nn][c4];     o.y = tile[nn][c4 + 1];
            o.z = tile[nn][c4 + 2]; o.w = tile[nn][c4 + 3];
            *(float4*)&g_xnt[((size_t)(b * N_ + nt * 128 + nn)) * C_ + cbase + c4] = o;
        }
        __syncthreads();
    }
}

// ---------------- 2) QKV: D[n][o] = xnt . Wqkv^T ---------------------------
__global__ __launch_bounds__(256, 2) void qkv_tc(const float* __restrict__ wq,
                                                 const float* __restrict__ bias) {
    extern __shared__ float sm[];
    float* sA = sm;
    float* sB = sm + 3 * 128 * PTF;
    const int n0 = blockIdx.x * 128, o0 = blockIdx.y * 128, b = blockIdx.z;
    float c[2][8][4] = {};
    gemm_cp<8>(g_xnt + ((size_t)(b * N_ + n0)) * C_, C_,
               wq + (size_t)o0 * C_, C_, sA, sB, c);

    const int lane = threadIdx.x & 31;
    const int wm = (threadIdx.x >> 5) & 3, wn = threadIdx.x >> 7;
    const int t = o0 >> 8;
    const int b4 = b * HEADS;
    #pragma unroll
    for (int i = 0; i < 2; i++) {
        int m = n0 + wm * 32 + i * 16 + (lane >> 2);
        #pragma unroll
        for (int j = 0; j < 8; j++) {
            int o = o0 + wn * 64 + j * 8 + (lane & 3) * 2;
            float b0v = bias[o], b1v = bias[o + 1];
            if (t < 2) {
                float* dst = (t == 0) ? g_q : g_k;
                int h = (o >> 6) & 3, d = o & 63;
                size_t rb = ((size_t)(b4 + h) * N_) * DH + d;
                float2 w0, w1;
                w0.x = c[i][j][0] + b0v; w0.y = c[i][j][1] + b1v;
                w1.x = c[i][j][2] + b0v; w1.y = c[i][j][3] + b1v;
                *(float2*)&dst[rb + (size_t)m * DH] = w0;
                *(float2*)&dst[rb + (size_t)(m + 8) * DH] = w1;
            } else {
                int og = o - 512;
                size_t rb = ((size_t)(b4 + (og >> 6)) * DH + (og & 63)) * N_;
                g_vt[rb + m]            = c[i][j][0] + b0v;
                g_vt[rb + N_ + m]       = c[i][j][1] + b1v;
                g_vt[rb + m + 8]        = c[i][j][2] + b0v;
                g_vt[rb + N_ + m + 8]   = c[i][j][3] + b1v;
            }
        }
    }
}

// ---------------- 3) fused flash attention ---------------------------------
// grid (N_/128, BH), 256 thr / 8 warps; warp w owns q rows [w*16, w*16+16).
// K processed in 16 tiles of 64 keys; Q in smem; cp.async double-buffered K/V.
__global__ __launch_bounds__(256, 2) void attn_fused() {
    extern __shared__ float sm[];
    float* sQ = sm;                        // 128 x PA
    float* sK = sQ + 128 * PA;             // 2 x 64 x PA   (K: [m][d])
    float* sV = sK + 2 * 64 * PA;          // 2 x 64 x PA   (Vt: [d][m64])

    const int tid = threadIdx.x, lane = tid & 31;
    const int wid = tid >> 5;
    const int tq = lane & 3, rq = lane >> 2;
    const int q0 = blockIdx.x * 128, bh = blockIdx.y;
    const int b = bh >> 2, hh = bh & 3;

    const float* gQ = g_q + ((size_t)bh * N_ + q0) * DH;
    const float* gK = g_k + (size_t)bh * N_ * DH;
    const float* gV = g_vt + (size_t)bh * DH * N_;

    const uint32_t suQ = su32(sQ), suK = su32(sK), suV = su32(sV);

    auto ldg_kv = [&](int t) {
        const uint32_t dK = suK + (t & 1) * 64 * PA * 4;
        const uint32_t dV = suV + (t & 1) * 64 * PA * 4;
        #pragma unroll
        for (int u = 0; u < 4; u++) {
            int unit = u * 256 + tid;
            int row = unit >> 4, cc = (unit & 15) * 4;
            cpa16(dK + (row * PA + cc) * 4, gK + (size_t)(t * 64 + row) * DH + cc);
            cpa16(dV + (row * PA + cc) * 4, gV + (size_t)row * N_ + t * 64 + cc);
        }
    };
    // Q tile + KV tile 0 -> group 0
    #pragma unroll
    for (int u = 0; u < 8; u++) {
        int unit = u * 256 + tid;
        int row = unit >> 4, cc = (unit & 15) * 4;
        cpa16(suQ + (row * PA + cc) * 4, gQ + (size_t)row * DH + cc);
    }
    ldg_kv(0); CP_COMMIT();

    float m0 = -1e30f, m1 = -1e30f, l0 = 0.f, l1 = 0.f;
    float co[8][4] = {};
    const float CE = 0.18033688011112042f;   // log2(e)/8

    const int s0l = (lane & ~3) | (tq >> 1);
    const int s1l = s0l + 2;
    const bool odd = tq & 1;

    for (int t = 0; t < 16; t++) {
        CP_WAIT(0);
        __syncthreads();
        if (t + 1 < 16) ldg_kv(t + 1);
        CP_COMMIT();
        const float* cK = sK + (t & 1) * 64 * PA;
        const float* cV = sV + (t & 1) * 64 * PA;

        // ---- S = Q . K^T : warp tile 16 x 64 ----
        float cs[8][4] = {};
        #pragma unroll
        for (int g = 0; g < 8; g++) {
            float a[4];
            const float* qr = sQ + (wid * 16 + rq) * PA + g * 8 + tq;
            a[0] = qr[0]; a[1] = qr[8 * PA]; a[2] = qr[4]; a[3] = qr[8 * PA + 4];
            #pragma unroll
            for (int j = 0; j < 8; j++) {
                const float* kr = cK + (j * 8 + rq) * PA + g * 8 + tq;
                mma_tf32(cs[j], a, kr[0], kr[4]);
            }
        }

        // ---- warp-private online softmax (raw s; exp2 with folded scale) --
        float mx0 = -1e30f, mx1 = -1e30f;
        #pragma unroll
        for (int j = 0; j < 8; j++) {
            mx0 = fmaxf(mx0, fmaxf(cs[j][0], cs[j][1]));
            mx1 = fmaxf(mx1, fmaxf(cs[j][2], cs[j][3]));
        }
        mx0 = fmaxf(mx0, __shfl_xor_sync(0xffffffffu, mx0, 1));
        mx0 = fmaxf(mx0, __shfl_xor_sync(0xffffffffu, mx0, 2));
        mx1 = fmaxf(mx1, __shfl_xor_sync(0xffffffffu, mx1, 1));
        mx1 = fmaxf(mx1, __shfl_xor_sync(0xffffffffu, mx1, 2));
        float nm0 = fmaxf(m0, mx0), nm1 = fmaxf(m1, mx1);
        float al0 = ex2f((m0 - nm0) * CE), al1 = ex2f((m1 - nm1) * CE);
        m0 = nm0; m1 = nm1;
        float ps0 = 0.f, ps1 = 0.f;
        #pragma unroll
        for (int j = 0; j < 8; j++) {
            cs[j][0] = ex2f((cs[j][0] - nm0) * CE);
            cs[j][1] = ex2f((cs[j][1] - nm0) * CE);
            cs[j][2] = ex2f((cs[j][2] - nm1) * CE);
            cs[j][3] = ex2f((cs[j][3] - nm1) * CE);
            ps0 += cs[j][0] + cs[j][1];
            ps1 += cs[j][2] + cs[j][3];
        }
        ps0 += __shfl_xor_sync(0xffffffffu, ps0, 1);
        ps0 += __shfl_xor_sync(0xffffffffu, ps0, 2);
        ps1 += __shfl_xor_sync(0xffffffffu, ps1, 1);
        ps1 += __shfl_xor_sync(0xffffffffu, ps1, 2);
        l0 = l0 * al0 + ps0;
        l1 = l1 * al1 + ps1;
        #pragma unroll
        for (int jd = 0; jd < 8; jd++) {
            co[jd][0] *= al0; co[jd][1] *= al0;
            co[jd][2] *= al1; co[jd][3] *= al1;
        }

        // ---- C-frag -> A-frag permutation (quad shuffles), in place ----
        #pragma unroll
        for (int j = 0; j < 8; j++) {
            float e0 = __shfl_sync(0xffffffffu, cs[j][0], s0l);
            float o0 = __shfl_sync(0xffffffffu, cs[j][1], s0l);
            float e1 = __shfl_sync(0xffffffffu, cs[j][0], s1l);
            float o1 = __shfl_sync(0xffffffffu, cs[j][1], s1l);
            float e2 = __shfl_sync(0xffffffffu, cs[j][2], s0l);
            float o2 = __shfl_sync(0xffffffffu, cs[j][3], s0l);
            float e3 = __shfl_sync(0xffffffffu, cs[j][2], s1l);
            float o3 = __shfl_sync(0xffffffffu, cs[j][3], s1l);
            cs[j][0] = tf32r(odd ? o0 : e0);
            cs[j][2] = tf32r(odd ? o1 : e1);
            cs[j][1] = tf32r(odd ? o2 : e2);
            cs[j][3] = tf32r(odd ? o3 : e3);
        }

        // ---- O += P . V : warp tile 16 x 64, k = 64 ----
        #pragma unroll
        for (int g = 0; g < 8; g++) {
            #pragma unroll
            for (int jd = 0; jd < 8; jd++) {
                const float* vr = cV + (jd * 8 + rq) * PA + g * 8 + tq;
                mma_tf32(co[jd], cs[g], vr[0], vr[4]);
            }
        }
    }

    // ---- epilogue: normalize + write g_ao[b][n][c] ----
    const float inv0 = 1.0f / l0, inv1 = 1.0f / l1;
    const int qrow = q0 + wid * 16 + rq;
    float* row0 = g_ao + ((size_t)(b * N_ + qrow)) * C_ + hh * DH;
    float* row1 = row0 + 8 * C_;
    #pragma unroll
    for (int jd = 0; jd < 8; jd++) {
        int d = jd * 8 + 2 * tq;
        float2 w0, w1;
        w0.x = co[jd][0] * inv0; w0.y = co[jd][1] * inv0;
        w1.x = co[jd][2] * inv1; w1.y = co[jd][3] * inv1;
        *(float2*)&row0[d] = w0;
        *(float2*)&row1[d] = w1;
    }
}

// ---------------- 4) proj + bias + residual: D[o][n] -----------------------
__global__ __launch_bounds__(256, 2) void proj_tc(const float* __restrict__ wp,
                                                  const float* __restrict__ bias,
                                                  const float* __restrict__ x,
                                                  float* __restrict__ out) {
    extern __shared__ float sm[];
    float* sA = sm;
    float* sB = sm + 3 * 128 * PTF;
    const int n0 = blockIdx.x * 128, o0 = blockIdx.y * 128, b = blockIdx.z;
    float c[2][8][4] = {};
    gemm_cp<8>(wp + (size_t)o0 * C_, C_,
               g_ao + ((size_t)(b * N_ + n0)) * C_, C_, sA, sB, c);

    const int lane = threadIdx.x & 31;
    const int wm = (threadIdx.x >> 5) & 3, wn = threadIdx.x >> 7;
    #pragma unroll
    for (int i = 0; i < 2; i++) {
        int o = o0 + wm * 32 + i * 16 + (lane >> 2);
        float pb0 = bias[o], pb1 = bias[o + 8];
        size_t r0b = ((size_t)(b * C_ + o)) * N_;
        size_t r1b = r0b + 8 * N_;
        #pragma unroll
        for (int j = 0; j < 8; j++) {
            int n = n0 + wn * 64 + j * 8 + (lane & 3) * 2;
            float2 sk0 = *(const float2*)&x[r0b + n];
            float2 sk1 = *(const float2*)&x[r1b + n];
            float2 w0, w1;
            w0.x = c[i][j][0] + pb0 + sk0.x; w0.y = c[i][j][1] + pb0 + sk0.y;
            w1.x = c[i][j][2] + pb1 + sk1.x; w1.y = c[i][j][3] + pb1 + sk1.y;
            *(float2*)&out[r0b + n] = w0;
            *(float2*)&out[r1b + n] = w1;
        }
    }
}

// ---------------------------------------------------------------------------
extern "C" void kernel_launch(void* const* d_in, const int* in_sizes, int n_in,
                              void* d_out, int out_size) {
    const float* x     = (const float*)d_in[0];
    const float* gn_w  = (const float*)d_in[1];
    const float* gn_b  = (const float*)d_in[2];
    const float* qkv_w = (const float*)d_in[3];
    const float* qkv_b = (const float*)d_in[4];
    const float* prj_w = (const float*)d_in[5];
    const float* prj_b = (const float*)d_in[6];
    float* out = (float*)d_out;

    const int smem_gemm = 3 * (128 + 128) * PTF * 4;          // 110592
    const int smem_attn = (128 + 4 * 64) * PA * 4;            // 104448
    cudaFuncSetAttribute(qkv_tc,     cudaFuncAttributeMaxDynamicSharedMemorySize, smem_gemm);
    cudaFuncSetAttribute(attn_fused, cudaFuncAttributeMaxDynamicSharedMemorySize, smem_attn);
    cudaFuncSetAttribute(proj_tc,    cudaFuncAttributeMaxDynamicSharedMemorySize, smem_gemm);

    gn_kernel<<<B_ * 8, 256>>>(x, gn_w, gn_b);
    qkv_tc<<<dim3(8, 6, B_), 256, smem_gemm>>>(qkv_w, qkv_b);
    attn_fused<<<dim3(8, BH), 256, smem_attn>>>();
    proj_tc<<<dim3(8, 2, B_), 256, smem_gemm>>>(prj_w, prj_b, x, out);
}

// round 11
// speedup vs baseline: 5.0494x; 1.0354x over previous
#include <cuda_runtime.h>
#include <math.h>
#include <stdint.h>

#define B_    16
#define C_    256
#define N_    1024
#define HEADS 4
#define DH    64
#define BH    (B_*HEADS)
#define PTF   36        // smem pitch (floats), 32-wide k panels (gemm core)
#define PA    68        // smem pitch (floats), 64-wide panels (attn)

// ---------------- scratch ---------------------------------------------------
__device__ __align__(256) float g_xnt[B_*N_*C_];          // [b][n][c]
__device__ __align__(256) float g_q  [BH*N_*DH];          // [bh][n][d]
__device__ __align__(256) float g_k  [BH*N_*DH];          // [bh][n][d]
__device__ __align__(256) float g_vt [BH*DH*N_];          // [bh][d][m]
__device__ __align__(256) float g_ao [B_*N_*C_];          // [b][n][c]

// ---------------- helpers ---------------------------------------------------
__device__ __forceinline__ uint32_t su32(const void* p) {
    uint32_t r;
    asm("{ .reg .u64 t; cvta.to.shared.u64 t, %1; cvt.u32.u64 %0, t; }"
        : "=r"(r) : "l"(p));
    return r;
}
__device__ __forceinline__ float ex2f(float x) {
    float r;
    asm("ex2.approx.f32 %0, %1;" : "=f"(r) : "f"(x));
    return r;
}
__device__ __forceinline__ void mma_tf32(float c[4], const float a[4],
                                         float b0, float b1) {
    asm volatile(
        "mma.sync.aligned.m16n8k8.row.col.f32.tf32.tf32.f32 "
        "{%0,%1,%2,%3}, {%4,%5,%6,%7}, {%8,%9}, {%0,%1,%2,%3};"
        : "+f"(c[0]), "+f"(c[1]), "+f"(c[2]), "+f"(c[3])
        : "r"(__float_as_uint(a[0])), "r"(__float_as_uint(a[1])),
          "r"(__float_as_uint(a[2])), "r"(__float_as_uint(a[3])),
          "r"(__float_as_uint(b0)),  "r"(__float_as_uint(b1)));
}
__device__ __forceinline__ void cpa16(uint32_t s, const void* g) {
    asm volatile("cp.async.ca.shared.global [%0], [%1], 16;"
                 :: "r"(s), "l"(g) : "memory");
}
#define CP_COMMIT() asm volatile("cp.async.commit_group;" ::: "memory")
#define CP_WAIT(n)  asm volatile("cp.async.wait_group %0;" :: "n"(n) : "memory")

// ---- 128x128 GEMM core: C = A(128xK,lda) . B(128xK,ldb)^T -----------------
// 256 thr / 8 warps (4m x 2n), BK=32, 2-stage cp.async double buffer,
// plain layout pitch PTF, ONE sync per k-tile.
template<int KT>
__device__ __forceinline__ void gemm_cp(const float* gA, int lda,
                                        const float* gB, int ldb,
                                        float* sA, float* sB,
                                        float (&c)[2][8][4]) {
    const int tid = threadIdx.x, lane = tid & 31;
    const int wm = (tid >> 5) & 3, wn = tid >> 7;
    const int tq = lane & 3, rq = lane >> 2;
    constexpr int BUF = 128 * PTF;
    const uint32_t suA = su32(sA), suB = su32(sB);

    auto ldg = [&](int kt) {
        const int st = kt & 1;
        const uint32_t dA = suA + st * BUF * 4;
        const uint32_t dB = suB + st * BUF * 4;
        #pragma unroll
        for (int u = 0; u < 4; u++) {
            int unit = u * 256 + tid;
            int row = unit >> 3, cc = (unit & 7) * 4;
            cpa16(dA + (row * PTF + cc) * 4, gA + (size_t)row * lda + kt * 32 + cc);
            cpa16(dB + (row * PTF + cc) * 4, gB + (size_t)row * ldb + kt * 32 + cc);
        }
    };

    ldg(0); CP_COMMIT();

    for (int kt = 0; kt < KT; kt++) {
        CP_WAIT(0);
        __syncthreads();          // all warps done with buffer (kt+1)&1
        if (kt + 1 < KT) { ldg(kt + 1); CP_COMMIT(); }
        const float* cA = sA + (kt & 1) * BUF;
        const float* cB = sB + (kt & 1) * BUF;
        #pragma unroll
        for (int g = 0; g < 4; g++) {
            float a[2][4];
            #pragma unroll
            for (int i = 0; i < 2; i++) {
                const float* ar = cA + (wm * 32 + i * 16 + rq) * PTF + g * 8 + tq;
                a[i][0] = ar[0];
                a[i][1] = ar[8 * PTF];
                a[i][2] = ar[4];
                a[i][3] = ar[8 * PTF + 4];
            }
            #pragma unroll
            for (int j = 0; j < 8; j++) {
                const float* br = cB + (wn * 64 + j * 8 + rq) * PTF + g * 8 + tq;
                #pragma unroll
                for (int i = 0; i < 2; i++)
                    mma_tf32(c[i][j], a[i], br[0], br[4]);
            }
        }
    }
}

// ---------------- 1) GroupNorm -> fp32 xnt[b][n][c] ------------------------
__global__ void gn_kernel(const float* __restrict__ x,
                          const float* __restrict__ w,
                          const float* __restrict__ bias) {
    const int blk = blockIdx.x;
    const size_t base = (size_t)blk * 32768;
    const int tid = threadIdx.x;

    double s = 0.0, s2 = 0.0;
    for (int i = tid; i < 8192; i += 256) {
        float4 v = *(const float4*)&x[base + i * 4];
        s  += (double)v.x + v.y + v.z + v.w;
        s2 += (double)v.x * v.x + (double)v.y * v.y
            + (double)v.z * v.z + (double)v.w * v.w;
    }
    __shared__ double rs[256], rs2[256];
    rs[tid] = s; rs2[tid] = s2;
    __syncthreads();
    for (int off = 128; off > 0; off >>= 1) {
        if (tid < off) { rs[tid] += rs[tid + off]; rs2[tid] += rs2[tid + off]; }
        __syncthreads();
    }
    __shared__ float smean, sinv;
    if (tid == 0) {
        double mu  = rs[0] * (1.0 / 32768.0);
        double var = rs2[0] * (1.0 / 32768.0) - mu * mu;
        smean = (float)mu;
        sinv  = (float)rsqrt(var + 1e-5);
    }
    __syncthreads();
    const int cbase = (blk & 7) * 32;
    __shared__ float ssc[32], ssb[32];
    if (tid < 32) {
        int cc = cbase + tid;
        float sc = sinv * w[cc];
        ssc[tid] = sc;
        ssb[tid] = bias[cc] - smean * sc;
    }
    __syncthreads();

    __shared__ float tile[128][33];
    const int b = blk >> 3;
    for (int nt = 0; nt < 8; nt++) {
        #pragma unroll
        for (int k2 = 0; k2 < 16; k2++) {
            int idx = tid + k2 * 256;
            int cc = idx >> 7, nn = idx & 127;
            tile[nn][cc] = x[base + (size_t)cc * 1024 + nt * 128 + nn]
                           * ssc[cc] + ssb[cc];
        }
        __syncthreads();
        #pragma unroll
        for (int k2 = 0; k2 < 4; k2++) {
            int idx = tid + k2 * 256;
            int nn = idx >> 3, c4 = (idx & 7) * 4;
            float4 o;
            o.x = tile[nn][c4];     o.y = tile[nn][c4 + 1];
            o.z = tile[nn][c4 + 2]; o.w = tile[nn][c4 + 3];
            *(float4*)&g_xnt[((size_t)(b * N_ + nt * 128 + nn)) * C_ + cbase + c4] = o;
        }
        __syncthreads();
    }
}

// ---------------- 2) QKV: D[n][o] = xnt . Wqkv^T ---------------------------
__global__ __launch_bounds__(256, 2) void qkv_tc(const float* __restrict__ wq,
                                                 const float* __restrict__ bias) {
    extern __shared__ float sm[];
    float* sA = sm;
    float* sB = sm + 2 * 128 * PTF;
    const int n0 = blockIdx.x * 128, o0 = blockIdx.y * 128, b = blockIdx.z;
    float c[2][8][4] = {};
    gemm_cp<8>(g_xnt + ((size_t)(b * N_ + n0)) * C_, C_,
               wq + (size_t)o0 * C_, C_, sA, sB, c);

    const int lane = threadIdx.x & 31;
    const int wm = (threadIdx.x >> 5) & 3, wn = threadIdx.x >> 7;
    const int t = o0 >> 8;
    const int b4 = b * HEADS;
    #pragma unroll
    for (int i = 0; i < 2; i++) {
        int m = n0 + wm * 32 + i * 16 + (lane >> 2);
        #pragma unroll
        for (int j = 0; j < 8; j++) {
            int o = o0 + wn * 64 + j * 8 + (lane & 3) * 2;
            float b0v = bias[o], b1v = bias[o + 1];
            if (t < 2) {
                float* dst = (t == 0) ? g_q : g_k;
                int h = (o >> 6) & 3, d = o & 63;
                size_t rb = ((size_t)(b4 + h) * N_) * DH + d;
                float2 w0, w1;
                w0.x = c[i][j][0] + b0v; w0.y = c[i][j][1] + b1v;
                w1.x = c[i][j][2] + b0v; w1.y = c[i][j][3] + b1v;
                *(float2*)&dst[rb + (size_t)m * DH] = w0;
                *(float2*)&dst[rb + (size_t)(m + 8) * DH] = w1;
            } else {
                int og = o - 512;
                size_t rb = ((size_t)(b4 + (og >> 6)) * DH + (og & 63)) * N_;
                g_vt[rb + m]            = c[i][j][0] + b0v;
                g_vt[rb + N_ + m]       = c[i][j][1] + b1v;
                g_vt[rb + m + 8]        = c[i][j][2] + b0v;
                g_vt[rb + N_ + m + 8]   = c[i][j][3] + b1v;
            }
        }
    }
}

// ---------------- 3) fused flash attention ---------------------------------
// grid (N_/128, BH), 256 thr / 8 warps; warp w owns q rows [w*16, w*16+16).
// K processed in 16 tiles of 64 keys; Q in smem; cp.async double-buffered K/V.
__global__ __launch_bounds__(256, 2) void attn_fused() {
    extern __shared__ float sm[];
    float* sQ = sm;                        // 128 x PA
    float* sK = sQ + 128 * PA;             // 2 x 64 x PA   (K: [m][d])
    float* sV = sK + 2 * 64 * PA;          // 2 x 64 x PA   (Vt: [d][m64])

    const int tid = threadIdx.x, lane = tid & 31;
    const int wid = tid >> 5;
    const int tq = lane & 3, rq = lane >> 2;
    const int q0 = blockIdx.x * 128, bh = blockIdx.y;
    const int b = bh >> 2, hh = bh & 3;

    const float* gQ = g_q + ((size_t)bh * N_ + q0) * DH;
    const float* gK = g_k + (size_t)bh * N_ * DH;
    const float* gV = g_vt + (size_t)bh * DH * N_;

    const uint32_t suQ = su32(sQ), suK = su32(sK), suV = su32(sV);

    auto ldg_kv = [&](int t) {
        const uint32_t dK = suK + (t & 1) * 64 * PA * 4;
        const uint32_t dV = suV + (t & 1) * 64 * PA * 4;
        #pragma unroll
        for (int u = 0; u < 4; u++) {
            int unit = u * 256 + tid;
            int row = unit >> 4, cc = (unit & 15) * 4;
            cpa16(dK + (row * PA + cc) * 4, gK + (size_t)(t * 64 + row) * DH + cc);
            cpa16(dV + (row * PA + cc) * 4, gV + (size_t)row * N_ + t * 64 + cc);
        }
    };
    // Q tile + KV tile 0 -> group 0
    #pragma unroll
    for (int u = 0; u < 8; u++) {
        int unit = u * 256 + tid;
        int row = unit >> 4, cc = (unit & 15) * 4;
        cpa16(suQ + (row * PA + cc) * 4, gQ + (size_t)row * DH + cc);
    }
    ldg_kv(0); CP_COMMIT();

    float m0 = -1e30f, m1 = -1e30f, l0 = 0.f, l1 = 0.f;
    float co[8][4] = {};
    const float CE = 0.18033688011112042f;   // log2(e)/8

    const int s0l = (lane & ~3) | (tq >> 1);
    const int s1l = s0l + 2;
    const bool odd = tq & 1;

    for (int t = 0; t < 16; t++) {
        CP_WAIT(0);
        __syncthreads();
        if (t + 1 < 16) { ldg_kv(t + 1); CP_COMMIT(); }
        const float* cK = sK + (t & 1) * 64 * PA;
        const float* cV = sV + (t & 1) * 64 * PA;

        // ---- S = Q . K^T : warp tile 16 x 64 ----
        float cs[8][4] = {};
        #pragma unroll
        for (int g = 0; g < 8; g++) {
            float a[4];
            const float* qr = sQ + (wid * 16 + rq) * PA + g * 8 + tq;
            a[0] = qr[0]; a[1] = qr[8 * PA]; a[2] = qr[4]; a[3] = qr[8 * PA + 4];
            #pragma unroll
            for (int j = 0; j < 8; j++) {
                const float* kr = cK + (j * 8 + rq) * PA + g * 8 + tq;
                mma_tf32(cs[j], a, kr[0], kr[4]);
            }
        }

        // ---- warp-private online softmax (raw s; exp2 with folded scale) --
        float mx0 = -1e30f, mx1 = -1e30f;
        #pragma unroll
        for (int j = 0; j < 8; j++) {
            mx0 = fmaxf(mx0, fmaxf(cs[j][0], cs[j][1]));
            mx1 = fmaxf(mx1, fmaxf(cs[j][2], cs[j][3]));
        }
        mx0 = fmaxf(mx0, __shfl_xor_sync(0xffffffffu, mx0, 1));
        mx0 = fmaxf(mx0, __shfl_xor_sync(0xffffffffu, mx0, 2));
        mx1 = fmaxf(mx1, __shfl_xor_sync(0xffffffffu, mx1, 1));
        mx1 = fmaxf(mx1, __shfl_xor_sync(0xffffffffu, mx1, 2));
        float nm0 = fmaxf(m0, mx0), nm1 = fmaxf(m1, mx1);
        float al0 = ex2f((m0 - nm0) * CE), al1 = ex2f((m1 - nm1) * CE);
        m0 = nm0; m1 = nm1;
        float ps0 = 0.f, ps1 = 0.f;
        #pragma unroll
        for (int j = 0; j < 8; j++) {
            cs[j][0] = ex2f((cs[j][0] - nm0) * CE);
            cs[j][1] = ex2f((cs[j][1] - nm0) * CE);
            cs[j][2] = ex2f((cs[j][2] - nm1) * CE);
            cs[j][3] = ex2f((cs[j][3] - nm1) * CE);
            ps0 += cs[j][0] + cs[j][1];
            ps1 += cs[j][2] + cs[j][3];
        }
        ps0 += __shfl_xor_sync(0xffffffffu, ps0, 1);
        ps0 += __shfl_xor_sync(0xffffffffu, ps0, 2);
        ps1 += __shfl_xor_sync(0xffffffffu, ps1, 1);
        ps1 += __shfl_xor_sync(0xffffffffu, ps1, 2);
        l0 = l0 * al0 + ps0;
        l1 = l1 * al1 + ps1;
        #pragma unroll
        for (int jd = 0; jd < 8; jd++) {
            co[jd][0] *= al0; co[jd][1] *= al0;
            co[jd][2] *= al1; co[jd][3] *= al1;
        }

        // ---- C-frag -> A-frag permutation (quad shuffles), in place ----
        #pragma unroll
        for (int j = 0; j < 8; j++) {
            float e0 = __shfl_sync(0xffffffffu, cs[j][0], s0l);
            float o0 = __shfl_sync(0xffffffffu, cs[j][1], s0l);
            float e1 = __shfl_sync(0xffffffffu, cs[j][0], s1l);
            float o1 = __shfl_sync(0xffffffffu, cs[j][1], s1l);
            float e2 = __shfl_sync(0xffffffffu, cs[j][2], s0l);
            float o2 = __shfl_sync(0xffffffffu, cs[j][3], s0l);
            float e3 = __shfl_sync(0xffffffffu, cs[j][2], s1l);
            float o3 = __shfl_sync(0xffffffffu, cs[j][3], s1l);
            cs[j][0] = odd ? o0 : e0;
            cs[j][2] = odd ? o1 : e1;
            cs[j][1] = odd ? o2 : e2;
            cs[j][3] = odd ? o3 : e3;
        }

        // ---- O += P . V : warp tile 16 x 64, k = 64 ----
        #pragma unroll
        for (int g = 0; g < 8; g++) {
            #pragma unroll
            for (int jd = 0; jd < 8; jd++) {
                const float* vr = cV + (jd * 8 + rq) * PA + g * 8 + tq;
                mma_tf32(co[jd], cs[g], vr[0], vr[4]);
            }
        }
    }

    // ---- epilogue: normalize + write g_ao[b][n][c] ----
    const float inv0 = 1.0f / l0, inv1 = 1.0f / l1;
    const int qrow = q0 + wid * 16 + rq;
    float* row0 = g_ao + ((size_t)(b * N_ + qrow)) * C_ + hh * DH;
    float* row1 = row0 + 8 * C_;
    #pragma unroll
    for (int jd = 0; jd < 8; jd++) {
        int d = jd * 8 + 2 * tq;
        float2 w0, w1;
        w0.x = co[jd][0] * inv0; w0.y = co[jd][1] * inv0;
        w1.x = co[jd][2] * inv1; w1.y = co[jd][3] * inv1;
        *(float2*)&row0[d] = w0;
        *(float2*)&row1[d] = w1;
    }
}

// ---------------- 4) proj + bias + residual: D[o][n] -----------------------
__global__ __launch_bounds__(256, 2) void proj_tc(const float* __restrict__ wp,
                                                  const float* __restrict__ bias,
                                                  const float* __restrict__ x,
                                                  float* __restrict__ out) {
    extern __shared__ float sm[];
    float* sA = sm;
    float* sB = sm + 2 * 128 * PTF;
    const int n0 = blockIdx.x * 128, o0 = blockIdx.y * 128, b = blockIdx.z;
    float c[2][8][4] = {};
    gemm_cp<8>(wp + (size_t)o0 * C_, C_,
               g_ao + ((size_t)(b * N_ + n0)) * C_, C_, sA, sB, c);

    const int lane = threadIdx.x & 31;
    const int wm = (threadIdx.x >> 5) & 3, wn = threadIdx.x >> 7;
    #pragma unroll
    for (int i = 0; i < 2; i++) {
        int o = o0 + wm * 32 + i * 16 + (lane >> 2);
        float pb0 = bias[o], pb1 = bias[o + 8];
        size_t r0b = ((size_t)(b * C_ + o)) * N_;
        size_t r1b = r0b + 8 * N_;
        #pragma unroll
        for (int j = 0; j < 8; j++) {
            int n = n0 + wn * 64 + j * 8 + (lane & 3) * 2;
            float2 sk0 = *(const float2*)&x[r0b + n];
            float2 sk1 = *(const float2*)&x[r1b + n];
            float2 w0, w1;
            w0.x = c[i][j][0] + pb0 + sk0.x; w0.y = c[i][j][1] + pb0 + sk0.y;
            w1.x = c[i][j][2] + pb1 + sk1.x; w1.y = c[i][j][3] + pb1 + sk1.y;
            *(float2*)&out[r0b + n] = w0;
            *(float2*)&out[r1b + n] = w1;
        }
    }
}

// ---------------------------------------------------------------------------
extern "C" void kernel_launch(void* const* d_in, const int* in_sizes, int n_in,
                              void* d_out, int out_size) {
    const float* x     = (const float*)d_in[0];
    const float* gn_w  = (const float*)d_in[1];
    const float* gn_b  = (const float*)d_in[2];
    const float* qkv_w = (const float*)d_in[3];
    const float* qkv_b = (const float*)d_in[4];
    const float* prj_w = (const float*)d_in[5];
    const float* prj_b = (const float*)d_in[6];
    float* out = (float*)d_out;

    const int smem_gemm = 2 * (128 + 128) * PTF * 4;          // 73728 -> 2 CTA/SM
    const int smem_attn = (128 + 4 * 64) * PA * 4;            // 104448
    cudaFuncSetAttribute(qkv_tc,     cudaFuncAttributeMaxDynamicSharedMemorySize, smem_gemm);
    cudaFuncSetAttribute(attn_fused, cudaFuncAttributeMaxDynamicSharedMemorySize, smem_attn);
    cudaFuncSetAttribute(proj_tc,    cudaFuncAttributeMaxDynamicSharedMemorySize, smem_gemm);

    gn_kernel<<<B_ * 8, 256>>>(x, gn_w, gn_b);
    qkv_tc<<<dim3(8, 6, B_), 256, smem_gemm>>>(qkv_w, qkv_b);
    attn_fused<<<dim3(8, BH), 256, smem_attn>>>();
    proj_tc<<<dim3(8, 2, B_), 256, smem_gemm>>>(prj_w, prj_b, x, out);
}